// round 5
// baseline (speedup 1.0000x reference)
#include <cuda_runtime.h>
#include <math.h>

// ---------------------------------------------------------------------------
// Problem constants
// ---------------------------------------------------------------------------
#define L_SEQ    2048
#define DMODEL   1024
#define DIN      2048   // D_INNER
#define DSTATE   16
#define DTRANK   64
#define XDBL_N   96     // DT_RANK + 2*D_STATE
#define KSPLIT   16     // split-K factor for the tall-skinny x_dbl GEMM

// ---------------------------------------------------------------------------
// Device scratch (no allocations allowed -> __device__ globals)
// ---------------------------------------------------------------------------
__device__ float g_xc   [L_SEQ * DIN];          // conv input  (x @ W_in, left half)
__device__ float g_zs   [L_SEQ * DIN];          // silu(z)     (right half)
__device__ float g_u    [L_SEQ * DIN];          // silu(conv(xc))
__device__ float g_delta[L_SEQ * DIN];          // softplus(dlt @ W_dt + b_dt)
__device__ float g_ys   [L_SEQ * DIN];          // y * silu(z)
__device__ float g_xdbl [L_SEQ * XDBL_N];       // u @ W_x
__device__ float g_part [KSPLIT * L_SEQ * XDBL_N]; // split-K partials
__device__ float g_A    [DIN * DSTATE];         // -exp(A_log)

// ---------------------------------------------------------------------------
// Helpers
// ---------------------------------------------------------------------------
__device__ __forceinline__ float siluf(float x) {
    return x / (1.0f + __expf(-x));
}
__device__ __forceinline__ float softplus_f(float x) {
    return x > 20.0f ? x : log1pf(__expf(x));
}

// ---------------------------------------------------------------------------
// A = -exp(A_log)
// ---------------------------------------------------------------------------
__global__ void aprep_kernel(const float* __restrict__ A_log) {
    int i = blockIdx.x * 256 + threadIdx.x;       // grid sized exactly
    g_A[i] = -__expf(A_log[i]);
}

// ---------------------------------------------------------------------------
// General fp32 SGEMM: C[M,N] = A[M,K] @ B[K,N], row-major, leading dims lda/ldb/ldc.
// Requires: M % 128 == 0, N % 128 == 0, K % 16 == 0 (true for all 3 uses).
// BM=BN=128, BK=16, 256 threads, 8x8 per thread, smem double buffered (1 sync/iter).
// EPI 0: plain store to C.
// EPI 1: split epilogue: block columns < N/2 -> C (xc), else silu -> C2 (zs). ldc = N/2.
// EPI 2: v = softplus(v + bias[col]); store to C.
// ---------------------------------------------------------------------------
template<int EPI>
__global__ __launch_bounds__(256, 2)
void sgemm_kernel(const float* __restrict__ A, int lda,
                  const float* __restrict__ B, int ldb,
                  float* __restrict__ C, int ldc,
                  float* __restrict__ C2,
                  const float* __restrict__ bias,
                  int M, int N, int K)
{
    __shared__ float As[2][16][132];   // transposed A tile, padded
    __shared__ float Bs[2][16][128];

    const int tid = threadIdx.x;
    const int bm  = blockIdx.y * 128;
    const int bn  = blockIdx.x * 128;

    // global-load mapping
    const int arow = tid >> 2;           // 0..63 (and +64)
    const int acol = (tid & 3) << 2;     // 0,4,8,12
    const int brow = tid >> 5;           // 0..7 (and +8)
    const int bcol = (tid & 31) << 2;    // 0..124

    // compute mapping: 16x16 thread grid of 8x8 micro-tiles
    const int tm = (tid >> 4) << 3;
    const int tn = (tid & 15) << 3;

    const float* Aptr  = A + (size_t)(bm + arow)      * lda + acol;
    const float* Aptr2 = A + (size_t)(bm + arow + 64) * lda + acol;
    const float* Bptr  = B + (size_t)brow       * ldb + bn + bcol;
    const float* Bptr2 = B + (size_t)(brow + 8) * ldb + bn + bcol;

    float acc[8][8];
#pragma unroll
    for (int i = 0; i < 8; ++i)
#pragma unroll
        for (int j = 0; j < 8; ++j) acc[i][j] = 0.0f;

    // prologue: tile 0 -> smem[0]
    {
        float4 a0 = *(const float4*)Aptr;
        float4 a1 = *(const float4*)Aptr2;
        float4 b0 = *(const float4*)Bptr;
        float4 b1 = *(const float4*)Bptr2;
        As[0][acol + 0][arow]      = a0.x;
        As[0][acol + 1][arow]      = a0.y;
        As[0][acol + 2][arow]      = a0.z;
        As[0][acol + 3][arow]      = a0.w;
        As[0][acol + 0][arow + 64] = a1.x;
        As[0][acol + 1][arow + 64] = a1.y;
        As[0][acol + 2][arow + 64] = a1.z;
        As[0][acol + 3][arow + 64] = a1.w;
        *(float4*)&Bs[0][brow][bcol]     = b0;
        *(float4*)&Bs[0][brow + 8][bcol] = b1;
    }
    __syncthreads();

    const int nk = K >> 4;
    int buf = 0;
    for (int kt = 0; kt < nk; ++kt) {
        float4 na0, na1, nb0, nb1;
        const bool has_next = (kt + 1 < nk);
        if (has_next) {
            const int kof = (kt + 1) << 4;
            na0 = *(const float4*)(Aptr  + kof);
            na1 = *(const float4*)(Aptr2 + kof);
            nb0 = *(const float4*)(Bptr  + (size_t)kof * ldb);
            nb1 = *(const float4*)(Bptr2 + (size_t)kof * ldb);
        }
#pragma unroll
        for (int k = 0; k < 16; ++k) {
            float af[8], bf[8];
            *(float4*)&af[0] = *(const float4*)&As[buf][k][tm];
            *(float4*)&af[4] = *(const float4*)&As[buf][k][tm + 4];
            *(float4*)&bf[0] = *(const float4*)&Bs[buf][k][tn];
            *(float4*)&bf[4] = *(const float4*)&Bs[buf][k][tn + 4];
#pragma unroll
            for (int i = 0; i < 8; ++i)
#pragma unroll
                for (int j = 0; j < 8; ++j)
                    acc[i][j] = fmaf(af[i], bf[j], acc[i][j]);
        }
        if (has_next) {
            buf ^= 1;
            As[buf][acol + 0][arow]      = na0.x;
            As[buf][acol + 1][arow]      = na0.y;
            As[buf][acol + 2][arow]      = na0.z;
            As[buf][acol + 3][arow]      = na0.w;
            As[buf][acol + 0][arow + 64] = na1.x;
            As[buf][acol + 1][arow + 64] = na1.y;
            As[buf][acol + 2][arow + 64] = na1.z;
            As[buf][acol + 3][arow + 64] = na1.w;
            *(float4*)&Bs[buf][brow][bcol]     = nb0;
            *(float4*)&Bs[buf][brow + 8][bcol] = nb1;
            __syncthreads();
        }
    }

    // epilogue
    const int row0 = bm + tm;
    if (EPI == 0) {
#pragma unroll
        for (int i = 0; i < 8; ++i) {
            float* p = C + (size_t)(row0 + i) * ldc + bn + tn;
            *(float4*)p       = make_float4(acc[i][0], acc[i][1], acc[i][2], acc[i][3]);
            *(float4*)(p + 4) = make_float4(acc[i][4], acc[i][5], acc[i][6], acc[i][7]);
        }
    } else if (EPI == 1) {
        const int half = N >> 1;
        const bool left = (bn < half);
        float* Dst = left ? C : C2;
        const int cb = left ? bn : (bn - half);
#pragma unroll
        for (int i = 0; i < 8; ++i) {
            float v[8];
#pragma unroll
            for (int j = 0; j < 8; ++j) v[j] = left ? acc[i][j] : siluf(acc[i][j]);
            float* p = Dst + (size_t)(row0 + i) * ldc + cb + tn;
            *(float4*)p       = make_float4(v[0], v[1], v[2], v[3]);
            *(float4*)(p + 4) = make_float4(v[4], v[5], v[6], v[7]);
        }
    } else {  // EPI == 2
        float bz[8];
#pragma unroll
        for (int j = 0; j < 8; ++j) bz[j] = bias[bn + tn + j];
#pragma unroll
        for (int i = 0; i < 8; ++i) {
            float v[8];
#pragma unroll
            for (int j = 0; j < 8; ++j) v[j] = softplus_f(acc[i][j] + bz[j]);
            float* p = C + (size_t)(row0 + i) * ldc + bn + tn;
            *(float4*)p       = make_float4(v[0], v[1], v[2], v[3]);
            *(float4*)(p + 4) = make_float4(v[4], v[5], v[6], v[7]);
        }
    }
}

// ---------------------------------------------------------------------------
// Causal depthwise conv (D_CONV=4) + silu:  u[t,d] = silu(b[d] + sum_j xc[t-3+j,d]*w[d,j])
// ---------------------------------------------------------------------------
__global__ void conv_silu_kernel(const float* __restrict__ cw,
                                 const float* __restrict__ cb)
{
    const int idx = blockIdx.x * 256 + threadIdx.x;   // grid sized exactly L*DIN
    const int t = idx >> 11;            // /DIN
    const int d = idx & (DIN - 1);
    const float4 w = ((const float4*)cw)[d];          // conv_w row [d,0..3]
    float acc = cb[d];
    if (t >= 3) acc = fmaf(g_xc[idx - 3 * DIN], w.x, acc);
    if (t >= 2) acc = fmaf(g_xc[idx - 2 * DIN], w.y, acc);
    if (t >= 1) acc = fmaf(g_xc[idx - 1 * DIN], w.z, acc);
    acc = fmaf(g_xc[idx], w.w, acc);
    g_u[idx] = siluf(acc);
}

// ---------------------------------------------------------------------------
// x_dbl = u @ W_x  (M=2048, N=96, K=2048) — split-K so enough blocks exist.
// Block: 128 rows x 96 cols over a K-chunk of DIN/KSPLIT. 256 threads, 8x6 each.
// Deterministic: partials to g_part, reduced by xdbl_reduce (no atomics).
// ---------------------------------------------------------------------------
__global__ __launch_bounds__(256)
void xdbl_kernel(const float* __restrict__ Wx)
{
    __shared__ float As[16][132];
    __shared__ float Bs[16][XDBL_N];
    const int tid = threadIdx.x;
    const int bm  = blockIdx.x * 128;
    const int k0  = blockIdx.y * (DIN / KSPLIT);      // chunk of 128

    const int arow = tid >> 2;
    const int acol = (tid & 3) << 2;
    const int tm = (tid >> 4) << 3;                   // 8 rows
    const int tn = (tid & 15) * 6;                    // 6 cols

    float acc[8][6];
#pragma unroll
    for (int i = 0; i < 8; ++i)
#pragma unroll
        for (int j = 0; j < 6; ++j) acc[i][j] = 0.0f;

    const int NT = (DIN / KSPLIT) >> 4;               // 8 k-tiles of 16
    for (int kt = 0; kt < NT; ++kt) {
        const int kof = k0 + (kt << 4);
        float4 a0 = *(const float4*)(g_u + (size_t)(bm + arow)      * DIN + kof + acol);
        float4 a1 = *(const float4*)(g_u + (size_t)(bm + arow + 64) * DIN + kof + acol);
        float bv[6];
#pragma unroll
        for (int i = 0; i < 6; ++i) {
            const int idx = tid + (i << 8);           // 0..1535 over 16x96
            bv[i] = Wx[(size_t)(kof + idx / XDBL_N) * XDBL_N + (idx % XDBL_N)];
        }
        __syncthreads();  // previous tile's compute done
        As[acol + 0][arow]      = a0.x;
        As[acol + 1][arow]      = a0.y;
        As[acol + 2][arow]      = a0.z;
        As[acol + 3][arow]      = a0.w;
        As[acol + 0][arow + 64] = a1.x;
        As[acol + 1][arow + 64] = a1.y;
        As[acol + 2][arow + 64] = a1.z;
        As[acol + 3][arow + 64] = a1.w;
#pragma unroll
        for (int i = 0; i < 6; ++i) {
            const int idx = tid + (i << 8);
            Bs[idx / XDBL_N][idx % XDBL_N] = bv[i];
        }
        __syncthreads();
#pragma unroll
        for (int k = 0; k < 16; ++k) {
            float af[8], bf[6];
            *(float4*)&af[0] = *(const float4*)&As[k][tm];
            *(float4*)&af[4] = *(const float4*)&As[k][tm + 4];
#pragma unroll
            for (int j = 0; j < 6; ++j) bf[j] = Bs[k][tn + j];
#pragma unroll
            for (int i = 0; i < 8; ++i)
#pragma unroll
                for (int j = 0; j < 6; ++j)
                    acc[i][j] = fmaf(af[i], bf[j], acc[i][j]);
        }
    }

    float* pp = g_part + (size_t)blockIdx.y * (L_SEQ * XDBL_N);
#pragma unroll
    for (int i = 0; i < 8; ++i)
#pragma unroll
        for (int j = 0; j < 6; ++j)
            pp[(size_t)(bm + tm + i) * XDBL_N + tn + j] = acc[i][j];
}

__global__ void xdbl_reduce_kernel()
{
    const int i = blockIdx.x * 256 + threadIdx.x;     // grid sized exactly L*96
    float s = 0.0f;
#pragma unroll
    for (int k = 0; k < KSPLIT; ++k) s += g_part[(size_t)k * (L_SEQ * XDBL_N) + i];
    g_xdbl[i] = s;
}

// ---------------------------------------------------------------------------
// Selective scan: one 16-lane group per channel d (lane = state n).
//   h = exp(delta*A)*h + delta*u*B ;  y = sum_n h*C + D*u ;  ys = y * silu(z)
// 8-step register double buffering so global (L2) latency hides behind compute.
// ---------------------------------------------------------------------------
__global__ __launch_bounds__(256)
void scan_kernel(const float* __restrict__ Dp)
{
    const int gid = blockIdx.x * 256 + threadIdx.x;   // 32768 lanes
    const int d = gid >> 4;
    const int n = gid & 15;

    const float Aa = g_A[(d << 4) + n];
    const float Dd = Dp[d];
    float h = 0.0f;

    const int UN = 8;
    float dt[UN], ut[UN], Bt[UN], Ct[UN], zt[UN];
#pragma unroll
    for (int i = 0; i < UN; ++i) {
        dt[i] = g_delta[(size_t)i * DIN + d];
        ut[i] = g_u    [(size_t)i * DIN + d];
        Bt[i] = g_xdbl [(size_t)i * XDBL_N + DTRANK + n];
        Ct[i] = g_xdbl [(size_t)i * XDBL_N + DTRANK + DSTATE + n];
        zt[i] = g_zs   [(size_t)i * DIN + d];
    }

    for (int t0 = 0; t0 < L_SEQ; t0 += UN) {
        float ndt[UN], nut[UN], nBt[UN], nCt[UN], nzt[UN];
        const int t1 = t0 + UN;
        if (t1 < L_SEQ) {
#pragma unroll
            for (int i = 0; i < UN; ++i) {
                ndt[i] = g_delta[(size_t)(t1 + i) * DIN + d];
                nut[i] = g_u    [(size_t)(t1 + i) * DIN + d];
                nBt[i] = g_xdbl [(size_t)(t1 + i) * XDBL_N + DTRANK + n];
                nCt[i] = g_xdbl [(size_t)(t1 + i) * XDBL_N + DTRANK + DSTATE + n];
                nzt[i] = g_zs   [(size_t)(t1 + i) * DIN + d];
            }
        }
#pragma unroll
        for (int i = 0; i < UN; ++i) {
            const float e = __expf(dt[i] * Aa);
            h = fmaf(e, h, dt[i] * ut[i] * Bt[i]);
            float p = h * Ct[i];
            p += __shfl_xor_sync(0xffffffffu, p, 8, 16);
            p += __shfl_xor_sync(0xffffffffu, p, 4, 16);
            p += __shfl_xor_sync(0xffffffffu, p, 2, 16);
            p += __shfl_xor_sync(0xffffffffu, p, 1, 16);
            if (n == 0)
                g_ys[(size_t)(t0 + i) * DIN + d] = (p + Dd * ut[i]) * zt[i];
        }
        if (t1 < L_SEQ) {
#pragma unroll
            for (int i = 0; i < UN; ++i) {
                dt[i] = ndt[i]; ut[i] = nut[i]; Bt[i] = nBt[i]; Ct[i] = nCt[i]; zt[i] = nzt[i];
            }
        }
    }
}

// ---------------------------------------------------------------------------
// kernel_launch
// ---------------------------------------------------------------------------
extern "C" void kernel_launch(void* const* d_in, const int* in_sizes, int n_in,
                              void* d_out, int out_size)
{
    const float* x      = (const float*)d_in[0];
    const float* W_in   = (const float*)d_in[1];
    const float* conv_w = (const float*)d_in[2];
    const float* conv_b = (const float*)d_in[3];
    const float* W_x    = (const float*)d_in[4];
    const float* W_dt   = (const float*)d_in[5];
    const float* b_dt   = (const float*)d_in[6];
    const float* A_log  = (const float*)d_in[7];
    const float* D_par  = (const float*)d_in[8];
    const float* W_out  = (const float*)d_in[9];
    float* out = (float*)d_out;

    float *p_xc, *p_zs, *p_delta, *p_ys, *p_xdbl;
    cudaGetSymbolAddress((void**)&p_xc,    g_xc);
    cudaGetSymbolAddress((void**)&p_zs,    g_zs);
    cudaGetSymbolAddress((void**)&p_delta, g_delta);
    cudaGetSymbolAddress((void**)&p_ys,    g_ys);
    cudaGetSymbolAddress((void**)&p_xdbl,  g_xdbl);

    // 1. A = -exp(A_log)
    aprep_kernel<<<(DIN * DSTATE) / 256, 256>>>(A_log);

    // 2. xz = x @ W_in ; split into xc and silu(z)
    sgemm_kernel<1><<<dim3(2 * DIN / 128, L_SEQ / 128), 256>>>(
        x, DMODEL, W_in, 2 * DIN, p_xc, DIN, p_zs, nullptr,
        L_SEQ, 2 * DIN, DMODEL);

    // 3. u = silu(causal_conv(xc))
    conv_silu_kernel<<<(L_SEQ * DIN) / 256, 256>>>(conv_w, conv_b);

    // 4. x_dbl = u @ W_x  (split-K + deterministic reduce)
    xdbl_kernel<<<dim3(L_SEQ / 128, KSPLIT), 256>>>(W_x);
    xdbl_reduce_kernel<<<(L_SEQ * XDBL_N) / 256, 256>>>();

    // 5. delta = softplus(x_dbl[:, :64] @ W_dt + b_dt)
    sgemm_kernel<2><<<dim3(DIN / 128, L_SEQ / 128), 256>>>(
        p_xdbl, XDBL_N, W_dt, DIN, p_delta, DIN, nullptr, b_dt,
        L_SEQ, DIN, DTRANK);

    // 6. selective scan -> ys = y * silu(z)
    scan_kernel<<<(DIN * DSTATE) / 256, 256>>>(D_par);

    // 7. out = ys @ W_out
    sgemm_kernel<0><<<dim3(DMODEL / 128, L_SEQ / 128), 256>>>(
        p_ys, DIN, W_out, DMODEL, out, DMODEL, nullptr, nullptr,
        L_SEQ, DMODEL, DIN);
}

// round 7
// speedup vs baseline: 2.1474x; 2.1474x over previous
#include <cuda_runtime.h>
#include <cuda_bf16.h>
#include <math.h>
#include <stdint.h>

// ---------------------------------------------------------------------------
// Problem constants
// ---------------------------------------------------------------------------
#define L_SEQ    2048
#define DMODEL   1024
#define DIN      2048   // D_INNER
#define DSTATE   16
#define DTRANK   64
#define XDBL_N   96     // DT_RANK + 2*D_STATE
#define KSPLIT   32     // split-K factor for the tall-skinny x_dbl GEMM

#define K1P (3 * DMODEL)   // 3072 : split-K' for GEMM1
#define K3P (3 * DIN)      // 6144 : split-K' for GEMM3

// ---------------------------------------------------------------------------
// Device scratch (no allocations allowed -> __device__ globals)
// ---------------------------------------------------------------------------
__device__ float g_xc   [L_SEQ * DIN];
__device__ float g_zs   [L_SEQ * DIN];
__device__ float g_u    [L_SEQ * DIN];
__device__ float g_delta[L_SEQ * DIN];
__device__ float g_ys   [L_SEQ * DIN];
__device__ float g_xdbl [L_SEQ * XDBL_N];
__device__ float g_part [KSPLIT * L_SEQ * XDBL_N];
__device__ float g_A    [DIN * DSTATE];

// bf16 split buffers (16B-aligned for cp.async / uint4)
__device__ __align__(128) __nv_bfloat16 g_A1[L_SEQ * K1P];     // [hi|lo|hi] of x
__device__ __align__(128) __nv_bfloat16 g_B1[2 * DIN * K1P];   // [hi|hi|lo] of W_in^T
__device__ __align__(128) __nv_bfloat16 g_A3[L_SEQ * K3P];     // split of ys
__device__ __align__(128) __nv_bfloat16 g_B3[DMODEL * K3P];    // split of W_out^T

// ---------------------------------------------------------------------------
// Helpers
// ---------------------------------------------------------------------------
__device__ __forceinline__ float siluf(float x) {
    return x / (1.0f + __expf(-x));
}
__device__ __forceinline__ float softplus_f(float x) {
    return x > 20.0f ? x : log1pf(__expf(x));
}
static __device__ __forceinline__ uint32_t smem_u32(const void* p) {
    uint32_t a;
    asm("{ .reg .u64 t; cvta.to.shared.u64 t, %1; cvt.u32.u64 %0, t; }" : "=r"(a) : "l"(p));
    return a;
}
static __device__ __forceinline__ void cp_async16(uint32_t saddr, const void* gptr) {
    asm volatile("cp.async.cg.shared.global [%0], [%1], 16;" :: "r"(saddr), "l"(gptr));
}

// ---------------------------------------------------------------------------
// A = -exp(A_log)
// ---------------------------------------------------------------------------
__global__ void aprep_kernel(const float* __restrict__ A_log) {
    int i = blockIdx.x * 256 + threadIdx.x;
    g_A[i] = -__expf(A_log[i]);
}

// ---------------------------------------------------------------------------
// Split activation fp32 -> bf16 [hi | lo | hi], row stride 3K.
// ---------------------------------------------------------------------------
__global__ void split_act_kernel(const float* __restrict__ in,
                                 __nv_bfloat16* __restrict__ out, int K)
{
    const int idx = blockIdx.x * 256 + threadIdx.x;     // exactly M*K
    const int r = idx / K;
    const int c = idx - r * K;
    float v = in[idx];
    __nv_bfloat16 h = __float2bfloat16(v);
    __nv_bfloat16 l = __float2bfloat16(v - __bfloat162float(h));
    size_t base = (size_t)r * (3 * K);
    out[base + c]         = h;
    out[base + K + c]     = l;
    out[base + 2 * K + c] = h;
}

// ---------------------------------------------------------------------------
// Transpose + split weights: W[K,N] fp32 -> out[N, 3K] bf16 as [hi | hi | lo].
// grid (N/32, K/32), 256 threads (32x8), smem-tiled transpose.
// ---------------------------------------------------------------------------
__global__ void wsplit_kernel(const float* __restrict__ W,
                              __nv_bfloat16* __restrict__ out, int K, int N)
{
    __shared__ float t[32][33];
    const int tx = threadIdx.x & 31;
    const int ty = threadIdx.x >> 5;    // 0..7
    const int col = blockIdx.x * 32 + tx;
#pragma unroll
    for (int i = 0; i < 4; ++i) {
        int row = blockIdx.y * 32 + ty + i * 8;
        t[ty + i * 8][tx] = W[(size_t)row * N + col];
    }
    __syncthreads();
    const int k = blockIdx.y * 32 + tx;
    const int K3 = 3 * K;
#pragma unroll
    for (int i = 0; i < 4; ++i) {
        int n = blockIdx.x * 32 + ty + i * 8;
        float v = t[tx][ty + i * 8];
        __nv_bfloat16 h = __float2bfloat16(v);
        __nv_bfloat16 l = __float2bfloat16(v - __bfloat162float(h));
        size_t base = (size_t)n * K3;
        out[base + k]         = h;
        out[base + K + k]     = h;
        out[base + 2 * K + k] = l;
    }
}

// ---------------------------------------------------------------------------
// HMMA (mma.sync m16n8k16 bf16) GEMM:  D[M,N] = A'[M,Kp] @ B'[N,Kp]^T
// BM=BN=128, BK=32, 256 threads = 8 warps (4 m x 2 n), warp tile 32x64.
// Smem rows padded to 40 bf16 (80B) -> conflict-free ldmatrix phases.
// cp.async double-buffered, 1 __syncthreads per BK iter.
// EPI 0: C[row*ldc + col] = v                 (GEMM3 -> out)
// EPI 1: col<2048 -> g_xc ; else silu -> g_zs (GEMM1)
// ---------------------------------------------------------------------------
#define SSTR 40   // smem row stride in bf16 (80 bytes)

template<int EPI>
__global__ __launch_bounds__(256, 2)
void mma_gemm_kernel(const __nv_bfloat16* __restrict__ Ab,
                     const __nv_bfloat16* __restrict__ Bb,
                     float* __restrict__ C, int Kp, int ldc)
{
    __shared__ __nv_bfloat16 sA[2][128 * SSTR];
    __shared__ __nv_bfloat16 sB[2][128 * SSTR];

    const int tid  = threadIdx.x;
    const int lane = tid & 31;
    const int wid  = tid >> 5;
    const int mw   = wid >> 1;       // 0..3
    const int nw   = wid & 1;        // 0..1
    const int bm   = blockIdx.y * 128;
    const int bn   = blockIdx.x * 128;

    const int KpV = Kp >> 3;                       // row stride in uint4
    const uint4* Ag = (const uint4*)Ab + (size_t)bm * KpV;
    const uint4* Bg = (const uint4*)Bb + (size_t)bn * KpV;

    const int lr = tid >> 2;        // load row 0..63 (and +64)
    const int lc = tid & 3;         // 16B chunk 0..3

    float acc[2][8][4];
#pragma unroll
    for (int mf = 0; mf < 2; ++mf)
#pragma unroll
        for (int nf = 0; nf < 8; ++nf)
#pragma unroll
            for (int q = 0; q < 4; ++q) acc[mf][nf][q] = 0.0f;

    // ldmatrix smem element offsets (within a buffer), precomputed per lane
    const int a_r0 = mw * 32 + (lane & 15);                 // + mf*16
    const int a_kc = ((lane >> 4) << 3);                    // + ks*16
    const int b_r0 = nw * 64 + (lane & 7) + ((lane >> 4) << 3);  // + nq*16
    const int b_kc = (((lane >> 3) & 1) << 3);              // + ks*16

    const int nkt = Kp >> 5;    // BK=32 iterations

    // prologue: tile 0 -> buffer 0
    {
        uint32_t sa = smem_u32(&sA[0][0]);
        uint32_t sb = smem_u32(&sB[0][0]);
        cp_async16(sa + (uint32_t)(lr * SSTR + lc * 8) * 2,        Ag + (size_t)lr * KpV + lc);
        cp_async16(sa + (uint32_t)((lr + 64) * SSTR + lc * 8) * 2, Ag + (size_t)(lr + 64) * KpV + lc);
        cp_async16(sb + (uint32_t)(lr * SSTR + lc * 8) * 2,        Bg + (size_t)lr * KpV + lc);
        cp_async16(sb + (uint32_t)((lr + 64) * SSTR + lc * 8) * 2, Bg + (size_t)(lr + 64) * KpV + lc);
        asm volatile("cp.async.commit_group;" ::: "memory");
    }
    asm volatile("cp.async.wait_group 0;" ::: "memory");
    __syncthreads();

    int buf = 0;
    for (int kt = 0; kt < nkt; ++kt) {
        const bool has_next = (kt + 1 < nkt);
        if (has_next) {
            const int kof = (kt + 1) << 2;   // uint4 offset
            uint32_t sa = smem_u32(&sA[buf ^ 1][0]);
            uint32_t sb = smem_u32(&sB[buf ^ 1][0]);
            cp_async16(sa + (uint32_t)(lr * SSTR + lc * 8) * 2,        Ag + (size_t)lr * KpV + kof + lc);
            cp_async16(sa + (uint32_t)((lr + 64) * SSTR + lc * 8) * 2, Ag + (size_t)(lr + 64) * KpV + kof + lc);
            cp_async16(sb + (uint32_t)(lr * SSTR + lc * 8) * 2,        Bg + (size_t)lr * KpV + kof + lc);
            cp_async16(sb + (uint32_t)((lr + 64) * SSTR + lc * 8) * 2, Bg + (size_t)(lr + 64) * KpV + kof + lc);
            asm volatile("cp.async.commit_group;" ::: "memory");
        }

        const uint32_t sa = smem_u32(&sA[buf][0]);
        const uint32_t sb = smem_u32(&sB[buf][0]);
#pragma unroll
        for (int ks = 0; ks < 2; ++ks) {
            uint32_t a[2][4];
#pragma unroll
            for (int mf = 0; mf < 2; ++mf) {
                uint32_t ad = sa + (uint32_t)((a_r0 + mf * 16) * SSTR + ks * 16 + a_kc) * 2;
                asm volatile("ldmatrix.sync.aligned.m8n8.x4.shared.b16 {%0,%1,%2,%3}, [%4];"
                             : "=r"(a[mf][0]), "=r"(a[mf][1]), "=r"(a[mf][2]), "=r"(a[mf][3])
                             : "r"(ad));
            }
            uint32_t bq[4][4];
#pragma unroll
            for (int nq = 0; nq < 4; ++nq) {
                uint32_t bd = sb + (uint32_t)((b_r0 + nq * 16) * SSTR + ks * 16 + b_kc) * 2;
                asm volatile("ldmatrix.sync.aligned.m8n8.x4.shared.b16 {%0,%1,%2,%3}, [%4];"
                             : "=r"(bq[nq][0]), "=r"(bq[nq][1]), "=r"(bq[nq][2]), "=r"(bq[nq][3])
                             : "r"(bd));
            }
#pragma unroll
            for (int mf = 0; mf < 2; ++mf)
#pragma unroll
                for (int nf = 0; nf < 8; ++nf) {
                    uint32_t b0 = bq[nf >> 1][(nf & 1) << 1];
                    uint32_t b1 = bq[nf >> 1][((nf & 1) << 1) + 1];
                    asm volatile(
                        "mma.sync.aligned.m16n8k16.row.col.f32.bf16.bf16.f32 "
                        "{%0,%1,%2,%3}, {%4,%5,%6,%7}, {%8,%9}, {%0,%1,%2,%3};"
                        : "+f"(acc[mf][nf][0]), "+f"(acc[mf][nf][1]),
                          "+f"(acc[mf][nf][2]), "+f"(acc[mf][nf][3])
                        : "r"(a[mf][0]), "r"(a[mf][1]), "r"(a[mf][2]), "r"(a[mf][3]),
                          "r"(b0), "r"(b1));
                }
        }

        if (has_next) {
            asm volatile("cp.async.wait_group 0;" ::: "memory");
            __syncthreads();
            buf ^= 1;
        }
    }

    // ---- epilogue: d-frag: (d0,d1)=(row L/4, col 2(L%4)), (d2,d3)=row+8
    const int rbase = bm + mw * 32 + (lane >> 2);
    const int cbase = bn + nw * 64 + ((lane & 3) << 1);
#pragma unroll
    for (int mf = 0; mf < 2; ++mf)
#pragma unroll
        for (int nf = 0; nf < 8; ++nf) {
            const int row = rbase + mf * 16;
            const int col = cbase + nf * 8;
            float2 v01 = make_float2(acc[mf][nf][0], acc[mf][nf][1]);
            float2 v23 = make_float2(acc[mf][nf][2], acc[mf][nf][3]);
            if (EPI == 0) {
                *(float2*)&C[(size_t)row * ldc + col]       = v01;
                *(float2*)&C[(size_t)(row + 8) * ldc + col] = v23;
            } else {
                if (col < 2048) {
                    *(float2*)&g_xc[(size_t)row * DIN + col]       = v01;
                    *(float2*)&g_xc[(size_t)(row + 8) * DIN + col] = v23;
                } else {
                    float2 s01 = make_float2(siluf(v01.x), siluf(v01.y));
                    float2 s23 = make_float2(siluf(v23.x), siluf(v23.y));
                    *(float2*)&g_zs[(size_t)row * DIN + col - 2048]       = s01;
                    *(float2*)&g_zs[(size_t)(row + 8) * DIN + col - 2048] = s23;
                }
            }
        }
}

// ---------------------------------------------------------------------------
// fp32 SGEMM for the small delta GEMM (K=64): softplus(v + bias[col]) -> C
// ---------------------------------------------------------------------------
__global__ __launch_bounds__(256, 2)
void sgemm_sp_kernel(const float* __restrict__ A, int lda,
                     const float* __restrict__ B, int ldb,
                     float* __restrict__ C, int ldc,
                     const float* __restrict__ bias,
                     int M, int N, int K)
{
    __shared__ float As[2][16][132];
    __shared__ float Bs[2][16][128];

    const int tid = threadIdx.x;
    const int bm  = blockIdx.y * 128;
    const int bn  = blockIdx.x * 128;

    const int arow = tid >> 2;
    const int acol = (tid & 3) << 2;
    const int brow = tid >> 5;
    const int bcol = (tid & 31) << 2;
    const int tm = (tid >> 4) << 3;
    const int tn = (tid & 15) << 3;

    const float* Aptr  = A + (size_t)(bm + arow)      * lda + acol;
    const float* Aptr2 = A + (size_t)(bm + arow + 64) * lda + acol;
    const float* Bptr  = B + (size_t)brow       * ldb + bn + bcol;
    const float* Bptr2 = B + (size_t)(brow + 8) * ldb + bn + bcol;

    float acc[8][8];
#pragma unroll
    for (int i = 0; i < 8; ++i)
#pragma unroll
        for (int j = 0; j < 8; ++j) acc[i][j] = 0.0f;

    {
        float4 a0 = *(const float4*)Aptr;
        float4 a1 = *(const float4*)Aptr2;
        float4 b0 = *(const float4*)Bptr;
        float4 b1 = *(const float4*)Bptr2;
        As[0][acol + 0][arow]      = a0.x; As[0][acol + 1][arow]      = a0.y;
        As[0][acol + 2][arow]      = a0.z; As[0][acol + 3][arow]      = a0.w;
        As[0][acol + 0][arow + 64] = a1.x; As[0][acol + 1][arow + 64] = a1.y;
        As[0][acol + 2][arow + 64] = a1.z; As[0][acol + 3][arow + 64] = a1.w;
        *(float4*)&Bs[0][brow][bcol]     = b0;
        *(float4*)&Bs[0][brow + 8][bcol] = b1;
    }
    __syncthreads();

    const int nk = K >> 4;
    int buf = 0;
    for (int kt = 0; kt < nk; ++kt) {
        float4 na0, na1, nb0, nb1;
        const bool has_next = (kt + 1 < nk);
        if (has_next) {
            const int kof = (kt + 1) << 4;
            na0 = *(const float4*)(Aptr  + kof);
            na1 = *(const float4*)(Aptr2 + kof);
            nb0 = *(const float4*)(Bptr  + (size_t)kof * ldb);
            nb1 = *(const float4*)(Bptr2 + (size_t)kof * ldb);
        }
#pragma unroll
        for (int k = 0; k < 16; ++k) {
            float af[8], bf[8];
            *(float4*)&af[0] = *(const float4*)&As[buf][k][tm];
            *(float4*)&af[4] = *(const float4*)&As[buf][k][tm + 4];
            *(float4*)&bf[0] = *(const float4*)&Bs[buf][k][tn];
            *(float4*)&bf[4] = *(const float4*)&Bs[buf][k][tn + 4];
#pragma unroll
            for (int i = 0; i < 8; ++i)
#pragma unroll
                for (int j = 0; j < 8; ++j)
                    acc[i][j] = fmaf(af[i], bf[j], acc[i][j]);
        }
        if (has_next) {
            buf ^= 1;
            As[buf][acol + 0][arow]      = na0.x; As[buf][acol + 1][arow]      = na0.y;
            As[buf][acol + 2][arow]      = na0.z; As[buf][acol + 3][arow]      = na0.w;
            As[buf][acol + 0][arow + 64] = na1.x; As[buf][acol + 1][arow + 64] = na1.y;
            As[buf][acol + 2][arow + 64] = na1.z; As[buf][acol + 3][arow + 64] = na1.w;
            *(float4*)&Bs[buf][brow][bcol]     = nb0;
            *(float4*)&Bs[buf][brow + 8][bcol] = nb1;
            __syncthreads();
        }
    }

    const int row0 = bm + tm;
    float bz[8];
#pragma unroll
    for (int j = 0; j < 8; ++j) bz[j] = bias[bn + tn + j];
#pragma unroll
    for (int i = 0; i < 8; ++i) {
        float v[8];
#pragma unroll
        for (int j = 0; j < 8; ++j) v[j] = softplus_f(acc[i][j] + bz[j]);
        float* p = C + (size_t)(row0 + i) * ldc + bn + tn;
        *(float4*)p       = make_float4(v[0], v[1], v[2], v[3]);
        *(float4*)(p + 4) = make_float4(v[4], v[5], v[6], v[7]);
    }
}

// ---------------------------------------------------------------------------
// Causal depthwise conv (D_CONV=4) + silu
// ---------------------------------------------------------------------------
__global__ void conv_silu_kernel(const float* __restrict__ cw,
                                 const float* __restrict__ cb)
{
    const int idx = blockIdx.x * 256 + threadIdx.x;
    const int t = idx >> 11;
    const int d = idx & (DIN - 1);
    const float4 w = ((const float4*)cw)[d];
    float acc = cb[d];
    if (t >= 3) acc = fmaf(g_xc[idx - 3 * DIN], w.x, acc);
    if (t >= 2) acc = fmaf(g_xc[idx - 2 * DIN], w.y, acc);
    if (t >= 1) acc = fmaf(g_xc[idx - 1 * DIN], w.z, acc);
    acc = fmaf(g_xc[idx], w.w, acc);
    g_u[idx] = siluf(acc);
}

// ---------------------------------------------------------------------------
// x_dbl = u @ W_x  (M=2048, N=96, K=2048) split-K=32 + deterministic reduce
// ---------------------------------------------------------------------------
__global__ __launch_bounds__(256)
void xdbl_kernel(const float* __restrict__ Wx)
{
    __shared__ float As[16][132];
    __shared__ float Bs[16][XDBL_N];
    const int tid = threadIdx.x;
    const int bm  = blockIdx.x * 128;
    const int k0  = blockIdx.y * (DIN / KSPLIT);

    const int arow = tid >> 2;
    const int acol = (tid & 3) << 2;
    const int tm = (tid >> 4) << 3;
    const int tn = (tid & 15) * 6;

    float acc[8][6];
#pragma unroll
    for (int i = 0; i < 8; ++i)
#pragma unroll
        for (int j = 0; j < 6; ++j) acc[i][j] = 0.0f;

    const int NT = (DIN / KSPLIT) >> 4;
    for (int kt = 0; kt < NT; ++kt) {
        const int kof = k0 + (kt << 4);
        float4 a0 = *(const float4*)(g_u + (size_t)(bm + arow)      * DIN + kof + acol);
        float4 a1 = *(const float4*)(g_u + (size_t)(bm + arow + 64) * DIN + kof + acol);
        float bv[6];
#pragma unroll
        for (int i = 0; i < 6; ++i) {
            const int idx = tid + (i << 8);
            bv[i] = Wx[(size_t)(kof + idx / XDBL_N) * XDBL_N + (idx % XDBL_N)];
        }
        __syncthreads();
        As[acol + 0][arow]      = a0.x; As[acol + 1][arow]      = a0.y;
        As[acol + 2][arow]      = a0.z; As[acol + 3][arow]      = a0.w;
        As[acol + 0][arow + 64] = a1.x; As[acol + 1][arow + 64] = a1.y;
        As[acol + 2][arow + 64] = a1.z; As[acol + 3][arow + 64] = a1.w;
#pragma unroll
        for (int i = 0; i < 6; ++i) {
            const int idx = tid + (i << 8);
            Bs[idx / XDBL_N][idx % XDBL_N] = bv[i];
        }
        __syncthreads();
#pragma unroll
        for (int k = 0; k < 16; ++k) {
            float af[8], bf[6];
            *(float4*)&af[0] = *(const float4*)&As[k][tm];
            *(float4*)&af[4] = *(const float4*)&As[k][tm + 4];
#pragma unroll
            for (int j = 0; j < 6; ++j) bf[j] = Bs[k][tn + j];
#pragma unroll
            for (int i = 0; i < 8; ++i)
#pragma unroll
                for (int j = 0; j < 6; ++j)
                    acc[i][j] = fmaf(af[i], bf[j], acc[i][j]);
        }
    }

    float* pp = g_part + (size_t)blockIdx.y * (L_SEQ * XDBL_N);
#pragma unroll
    for (int i = 0; i < 8; ++i)
#pragma unroll
        for (int j = 0; j < 6; ++j)
            pp[(size_t)(bm + tm + i) * XDBL_N + tn + j] = acc[i][j];
}

__global__ void xdbl_reduce_kernel()
{
    const int i = blockIdx.x * 256 + threadIdx.x;
    float s = 0.0f;
#pragma unroll
    for (int k = 0; k < KSPLIT; ++k) s += g_part[(size_t)k * (L_SEQ * XDBL_N) + i];
    g_xdbl[i] = s;
}

// ---------------------------------------------------------------------------
// Selective scan (16 lanes per channel; shfl reduce over states)
// ---------------------------------------------------------------------------
__global__ __launch_bounds__(256)
void scan_kernel(const float* __restrict__ Dp)
{
    const int gid = blockIdx.x * 256 + threadIdx.x;
    const int d = gid >> 4;
    const int n = gid & 15;

    const float Aa = g_A[(d << 4) + n];
    const float Dd = Dp[d];
    float h = 0.0f;

    const int UN = 8;
    float dt[UN], ut[UN], Bt[UN], Ct[UN], zt[UN];
#pragma unroll
    for (int i = 0; i < UN; ++i) {
        dt[i] = g_delta[(size_t)i * DIN + d];
        ut[i] = g_u    [(size_t)i * DIN + d];
        Bt[i] = g_xdbl [(size_t)i * XDBL_N + DTRANK + n];
        Ct[i] = g_xdbl [(size_t)i * XDBL_N + DTRANK + DSTATE + n];
        zt[i] = g_zs   [(size_t)i * DIN + d];
    }

    for (int t0 = 0; t0 < L_SEQ; t0 += UN) {
        float ndt[UN], nut[UN], nBt[UN], nCt[UN], nzt[UN];
        const int t1 = t0 + UN;
        if (t1 < L_SEQ) {
#pragma unroll
            for (int i = 0; i < UN; ++i) {
                ndt[i] = g_delta[(size_t)(t1 + i) * DIN + d];
                nut[i] = g_u    [(size_t)(t1 + i) * DIN + d];
                nBt[i] = g_xdbl [(size_t)(t1 + i) * XDBL_N + DTRANK + n];
                nCt[i] = g_xdbl [(size_t)(t1 + i) * XDBL_N + DTRANK + DSTATE + n];
                nzt[i] = g_zs   [(size_t)(t1 + i) * DIN + d];
            }
        }
#pragma unroll
        for (int i = 0; i < UN; ++i) {
            const float e = __expf(dt[i] * Aa);
            h = fmaf(e, h, dt[i] * ut[i] * Bt[i]);
            float p = h * Ct[i];
            p += __shfl_xor_sync(0xffffffffu, p, 8, 16);
            p += __shfl_xor_sync(0xffffffffu, p, 4, 16);
            p += __shfl_xor_sync(0xffffffffu, p, 2, 16);
            p += __shfl_xor_sync(0xffffffffu, p, 1, 16);
            if (n == 0)
                g_ys[(size_t)(t0 + i) * DIN + d] = (p + Dd * ut[i]) * zt[i];
        }
        if (t1 < L_SEQ) {
#pragma unroll
            for (int i = 0; i < UN; ++i) {
                dt[i] = ndt[i]; ut[i] = nut[i]; Bt[i] = nBt[i]; Ct[i] = nCt[i]; zt[i] = nzt[i];
            }
        }
    }
}

// ---------------------------------------------------------------------------
// kernel_launch
// ---------------------------------------------------------------------------
extern "C" void kernel_launch(void* const* d_in, const int* in_sizes, int n_in,
                              void* d_out, int out_size)
{
    const float* x      = (const float*)d_in[0];
    const float* W_in   = (const float*)d_in[1];
    const float* conv_w = (const float*)d_in[2];
    const float* conv_b = (const float*)d_in[3];
    const float* W_x    = (const float*)d_in[4];
    const float* W_dt   = (const float*)d_in[5];
    const float* b_dt   = (const float*)d_in[6];
    const float* A_log  = (const float*)d_in[7];
    const float* D_par  = (const float*)d_in[8];
    const float* W_out  = (const float*)d_in[9];
    float* out = (float*)d_out;

    float *p_xdbl, *p_delta, *p_ys;
    __nv_bfloat16 *pA1, *pB1, *pA3, *pB3;
    cudaGetSymbolAddress((void**)&p_xdbl,  g_xdbl);
    cudaGetSymbolAddress((void**)&p_delta, g_delta);
    cudaGetSymbolAddress((void**)&p_ys,    g_ys);
    cudaGetSymbolAddress((void**)&pA1, g_A1);
    cudaGetSymbolAddress((void**)&pB1, g_B1);
    cudaGetSymbolAddress((void**)&pA3, g_A3);
    cudaGetSymbolAddress((void**)&pB3, g_B3);

    // 1. A = -exp(A_log)
    aprep_kernel<<<(DIN * DSTATE) / 256, 256>>>(A_log);

    // 2. bf16 split conversions
    split_act_kernel<<<(L_SEQ * DMODEL) / 256, 256>>>(x, pA1, DMODEL);
    wsplit_kernel<<<dim3((2 * DIN) / 32, DMODEL / 32), 256>>>(W_in, pB1, DMODEL, 2 * DIN);
    wsplit_kernel<<<dim3(DMODEL / 32, DIN / 32), 256>>>(W_out, pB3, DIN, DMODEL);

    // 3. GEMM1 (HMMA): xz = x @ W_in -> g_xc | silu -> g_zs
    mma_gemm_kernel<1><<<dim3((2 * DIN) / 128, L_SEQ / 128), 256>>>(
        pA1, pB1, nullptr, K1P, 0);

    // 4. u = silu(causal_conv(xc))
    conv_silu_kernel<<<(L_SEQ * DIN) / 256, 256>>>(conv_w, conv_b);

    // 5. x_dbl = u @ W_x  (split-K + deterministic reduce)
    xdbl_kernel<<<dim3(L_SEQ / 128, KSPLIT), 256>>>(W_x);
    xdbl_reduce_kernel<<<(L_SEQ * XDBL_N) / 256, 256>>>();

    // 6. delta = softplus(x_dbl[:, :64] @ W_dt + b_dt)  (fp32, K=64)
    sgemm_sp_kernel<<<dim3(DIN / 128, L_SEQ / 128), 256>>>(
        p_xdbl, XDBL_N, W_dt, DIN, p_delta, DIN, b_dt,
        L_SEQ, DIN, DTRANK);

    // 7. selective scan -> ys = y * silu(z)
    scan_kernel<<<(DIN * DSTATE) / 256, 256>>>(D_par);

    // 8. GEMM3 (HMMA): out = ys @ W_out
    split_act_kernel<<<(L_SEQ * DIN) / 256, 256>>>(p_ys, pA3, DIN);
    mma_gemm_kernel<0><<<dim3(DMODEL / 128, L_SEQ / 128), 256>>>(
        pA3, pB3, out, K3P, DMODEL);
}

// round 8
// speedup vs baseline: 2.2387x; 1.0425x over previous
#include <cuda_runtime.h>
#include <cuda_bf16.h>
#include <math.h>
#include <stdint.h>

// ---------------------------------------------------------------------------
// Problem constants
// ---------------------------------------------------------------------------
#define L_SEQ    2048
#define DMODEL   1024
#define DIN      2048   // D_INNER
#define DSTATE   16
#define DTRANK   64
#define XDBL_N   96     // DT_RANK + 2*D_STATE
#define KSPLIT   32     // split-K factor for the tall-skinny x_dbl GEMM

#define K1P (3 * DMODEL)   // 3072 : split-K' for GEMM1
#define K3P (3 * DIN)      // 6144 : split-K' for GEMM3

// ---------------------------------------------------------------------------
// Device scratch (no allocations allowed -> __device__ globals)
// ---------------------------------------------------------------------------
__device__ float g_xc   [L_SEQ * DIN];
__device__ float g_zs   [L_SEQ * DIN];
__device__ float g_u    [L_SEQ * DIN];
__device__ float g_delta[L_SEQ * DIN];
__device__ float g_ys   [L_SEQ * DIN];
__device__ float g_xdbl [L_SEQ * XDBL_N];
__device__ float g_part [KSPLIT * L_SEQ * XDBL_N];
__device__ float g_A    [DIN * DSTATE];

// bf16 split buffers (16B-aligned for cp.async / uint4)
__device__ __align__(128) __nv_bfloat16 g_A1[L_SEQ * K1P];     // [hi|lo|hi] of x
__device__ __align__(128) __nv_bfloat16 g_B1[2 * DIN * K1P];   // [hi|hi|lo] of W_in^T
__device__ __align__(128) __nv_bfloat16 g_A3[L_SEQ * K3P];     // split of ys
__device__ __align__(128) __nv_bfloat16 g_B3[DMODEL * K3P];    // split of W_out^T

// ---------------------------------------------------------------------------
// Helpers
// ---------------------------------------------------------------------------
__device__ __forceinline__ float siluf(float x) {
    return x / (1.0f + __expf(-x));
}
__device__ __forceinline__ float softplus_f(float x) {
    return x > 20.0f ? x : log1pf(__expf(x));
}
static __device__ __forceinline__ uint32_t smem_u32(const void* p) {
    uint32_t a;
    asm("{ .reg .u64 t; cvta.to.shared.u64 t, %1; cvt.u32.u64 %0, t; }" : "=r"(a) : "l"(p));
    return a;
}
static __device__ __forceinline__ void cp_async16(uint32_t saddr, const void* gptr) {
    asm volatile("cp.async.cg.shared.global [%0], [%1], 16;" :: "r"(saddr), "l"(gptr));
}

// ---------------------------------------------------------------------------
// A = -exp(A_log)
// ---------------------------------------------------------------------------
__global__ void aprep_kernel(const float* __restrict__ A_log) {
    int i = blockIdx.x * 256 + threadIdx.x;
    g_A[i] = -__expf(A_log[i]);
}

// ---------------------------------------------------------------------------
// Split activation fp32 -> bf16 [hi | lo | hi], row stride 3K.
// ---------------------------------------------------------------------------
__global__ void split_act_kernel(const float* __restrict__ in,
                                 __nv_bfloat16* __restrict__ out, int K)
{
    const int idx = blockIdx.x * 256 + threadIdx.x;     // exactly M*K
    const int r = idx / K;
    const int c = idx - r * K;
    float v = in[idx];
    __nv_bfloat16 h = __float2bfloat16(v);
    __nv_bfloat16 l = __float2bfloat16(v - __bfloat162float(h));
    size_t base = (size_t)r * (3 * K);
    out[base + c]         = h;
    out[base + K + c]     = l;
    out[base + 2 * K + c] = h;
}

// ---------------------------------------------------------------------------
// Transpose + split weights: W[K,N] fp32 -> out[N, 3K] bf16 as [hi | hi | lo].
// ---------------------------------------------------------------------------
__global__ void wsplit_kernel(const float* __restrict__ W,
                              __nv_bfloat16* __restrict__ out, int K, int N)
{
    __shared__ float t[32][33];
    const int tx = threadIdx.x & 31;
    const int ty = threadIdx.x >> 5;    // 0..7
    const int col = blockIdx.x * 32 + tx;
#pragma unroll
    for (int i = 0; i < 4; ++i) {
        int row = blockIdx.y * 32 + ty + i * 8;
        t[ty + i * 8][tx] = W[(size_t)row * N + col];
    }
    __syncthreads();
    const int k = blockIdx.y * 32 + tx;
    const int K3 = 3 * K;
#pragma unroll
    for (int i = 0; i < 4; ++i) {
        int n = blockIdx.x * 32 + ty + i * 8;
        float v = t[tx][ty + i * 8];
        __nv_bfloat16 h = __float2bfloat16(v);
        __nv_bfloat16 l = __float2bfloat16(v - __bfloat162float(h));
        size_t base = (size_t)n * K3;
        out[base + k]         = h;
        out[base + K + k]     = h;
        out[base + 2 * K + k] = l;
    }
}

// ---------------------------------------------------------------------------
// HMMA (mma.sync m16n8k16 bf16) GEMM:  D[M,N] = A'[M,Kp] @ B'[N,Kp]^T
// BM=MF*64 (MF=2 ->128, MF=1 ->64), BN=128, BK=32, 256 threads = 8 warps
// (4m x 2n); warp tile (MF*16)x64. Smem rows padded to 40 bf16 -> conflict-
// free ldmatrix. cp.async double-buffered; register fragment double-buffer
// pipelines LDS latency behind MMAs.
// EPI 0: C[row*ldc + col] = v                 (GEMM3 -> out)
// EPI 1: col<2048 -> g_xc ; else silu -> g_zs (GEMM1)
// ---------------------------------------------------------------------------
#define SSTR 40   // smem row stride in bf16 (80 bytes)

template<int MF>
static __device__ __forceinline__ void ld_frags(
    uint32_t sa, uint32_t sb, int a_r0, int a_kc, int b_r0, int b_kc, int ks,
    uint32_t (&a)[MF][4], uint32_t (&b)[4][4])
{
#pragma unroll
    for (int mf = 0; mf < MF; ++mf) {
        uint32_t ad = sa + (uint32_t)((a_r0 + mf * 16) * SSTR + ks * 16 + a_kc) * 2;
        asm volatile("ldmatrix.sync.aligned.m8n8.x4.shared.b16 {%0,%1,%2,%3}, [%4];"
                     : "=r"(a[mf][0]), "=r"(a[mf][1]), "=r"(a[mf][2]), "=r"(a[mf][3])
                     : "r"(ad));
    }
#pragma unroll
    for (int nq = 0; nq < 4; ++nq) {
        uint32_t bd = sb + (uint32_t)((b_r0 + nq * 16) * SSTR + ks * 16 + b_kc) * 2;
        asm volatile("ldmatrix.sync.aligned.m8n8.x4.shared.b16 {%0,%1,%2,%3}, [%4];"
                     : "=r"(b[nq][0]), "=r"(b[nq][1]), "=r"(b[nq][2]), "=r"(b[nq][3])
                     : "r"(bd));
    }
}

template<int MF>
static __device__ __forceinline__ void do_mma(
    float (&acc)[MF][8][4], uint32_t (&a)[MF][4], uint32_t (&b)[4][4])
{
#pragma unroll
    for (int mf = 0; mf < MF; ++mf)
#pragma unroll
        for (int nf = 0; nf < 8; ++nf) {
            uint32_t b0 = b[nf >> 1][(nf & 1) << 1];
            uint32_t b1 = b[nf >> 1][((nf & 1) << 1) + 1];
            asm volatile(
                "mma.sync.aligned.m16n8k16.row.col.f32.bf16.bf16.f32 "
                "{%0,%1,%2,%3}, {%4,%5,%6,%7}, {%8,%9}, {%0,%1,%2,%3};"
                : "+f"(acc[mf][nf][0]), "+f"(acc[mf][nf][1]),
                  "+f"(acc[mf][nf][2]), "+f"(acc[mf][nf][3])
                : "r"(a[mf][0]), "r"(a[mf][1]), "r"(a[mf][2]), "r"(a[mf][3]),
                  "r"(b0), "r"(b1));
        }
}

template<int EPI, int MF>
__global__ __launch_bounds__(256, 2)
void mma_gemm_kernel(const __nv_bfloat16* __restrict__ Ab,
                     const __nv_bfloat16* __restrict__ Bb,
                     float* __restrict__ C, int Kp, int ldc)
{
    constexpr int BM = MF * 64;
    __shared__ __nv_bfloat16 sA[2][BM * SSTR];
    __shared__ __nv_bfloat16 sB[2][128 * SSTR];

    const int tid  = threadIdx.x;
    const int lane = tid & 31;
    const int wid  = tid >> 5;
    const int mw   = wid >> 1;       // 0..3
    const int nw   = wid & 1;        // 0..1
    const int bm   = blockIdx.y * BM;
    const int bn   = blockIdx.x * 128;

    const int KpV = Kp >> 3;                       // row stride in uint4
    const uint4* Ag = (const uint4*)Ab + (size_t)bm * KpV;
    const uint4* Bg = (const uint4*)Bb + (size_t)bn * KpV;

    const int lr = tid >> 2;        // load row 0..63 (and +64)
    const int lc = tid & 3;         // 16B chunk 0..3

    float acc[MF][8][4];
#pragma unroll
    for (int mf = 0; mf < MF; ++mf)
#pragma unroll
        for (int nf = 0; nf < 8; ++nf)
#pragma unroll
            for (int q = 0; q < 4; ++q) acc[mf][nf][q] = 0.0f;

    // ldmatrix lane offsets
    const int a_r0 = mw * (16 * MF) + (lane & 15);
    const int a_kc = ((lane >> 4) << 3);
    const int b_r0 = nw * 64 + (lane & 7) + ((lane >> 4) << 3);
    const int b_kc = (((lane >> 3) & 1) << 3);

    const int nkt = Kp >> 5;    // BK=32 iterations

    // load tile kt into buffer b
    auto load_tile = [&](int b, int kt) {
        const int kof = kt << 2;   // uint4 offset
        uint32_t sa = smem_u32(&sA[b][0]);
        uint32_t sb = smem_u32(&sB[b][0]);
        cp_async16(sa + (uint32_t)(lr * SSTR + lc * 8) * 2, Ag + (size_t)lr * KpV + kof + lc);
        if (MF == 2)
            cp_async16(sa + (uint32_t)((lr + 64) * SSTR + lc * 8) * 2,
                       Ag + (size_t)(lr + 64) * KpV + kof + lc);
        cp_async16(sb + (uint32_t)(lr * SSTR + lc * 8) * 2, Bg + (size_t)lr * KpV + kof + lc);
        cp_async16(sb + (uint32_t)((lr + 64) * SSTR + lc * 8) * 2,
                   Bg + (size_t)(lr + 64) * KpV + kof + lc);
        asm volatile("cp.async.commit_group;" ::: "memory");
    };

    // prologue
    load_tile(0, 0);
    asm volatile("cp.async.wait_group 0;" ::: "memory");
    __syncthreads();

    uint32_t fa0[MF][4], fb0[4][4];   // frag set A (current ks)
    uint32_t fa1[MF][4], fb1[4][4];   // frag set B (next ks)
    {
        uint32_t sa = smem_u32(&sA[0][0]);
        uint32_t sb = smem_u32(&sB[0][0]);
        ld_frags<MF>(sa, sb, a_r0, a_kc, b_r0, b_kc, 0, fa0, fb0);
    }

    int buf = 0;
    for (int kt = 0; kt < nkt; ++kt) {
        const bool has_next = (kt + 1 < nkt);
        if (has_next) load_tile(buf ^ 1, kt + 1);

        // ks=1 frags from current buffer; MMA ks=0 hides the LDS latency
        {
            uint32_t sa = smem_u32(&sA[buf][0]);
            uint32_t sb = smem_u32(&sB[buf][0]);
            ld_frags<MF>(sa, sb, a_r0, a_kc, b_r0, b_kc, 1, fa1, fb1);
        }
        do_mma<MF>(acc, fa0, fb0);

        if (has_next) {
            asm volatile("cp.async.wait_group 0;" ::: "memory");
            __syncthreads();
            uint32_t sa = smem_u32(&sA[buf ^ 1][0]);
            uint32_t sb = smem_u32(&sB[buf ^ 1][0]);
            ld_frags<MF>(sa, sb, a_r0, a_kc, b_r0, b_kc, 0, fa0, fb0);
        }
        do_mma<MF>(acc, fa1, fb1);
        buf ^= 1;
    }

    // ---- epilogue
    const int rbase = bm + mw * (16 * MF) + (lane >> 2);
    const int cbase = bn + nw * 64 + ((lane & 3) << 1);
#pragma unroll
    for (int mf = 0; mf < MF; ++mf)
#pragma unroll
        for (int nf = 0; nf < 8; ++nf) {
            const int row = rbase + mf * 16;
            const int col = cbase + nf * 8;
            float2 v01 = make_float2(acc[mf][nf][0], acc[mf][nf][1]);
            float2 v23 = make_float2(acc[mf][nf][2], acc[mf][nf][3]);
            if (EPI == 0) {
                *(float2*)&C[(size_t)row * ldc + col]       = v01;
                *(float2*)&C[(size_t)(row + 8) * ldc + col] = v23;
            } else {
                if (col < 2048) {
                    *(float2*)&g_xc[(size_t)row * DIN + col]       = v01;
                    *(float2*)&g_xc[(size_t)(row + 8) * DIN + col] = v23;
                } else {
                    float2 s01 = make_float2(siluf(v01.x), siluf(v01.y));
                    float2 s23 = make_float2(siluf(v23.x), siluf(v23.y));
                    *(float2*)&g_zs[(size_t)row * DIN + col - 2048]       = s01;
                    *(float2*)&g_zs[(size_t)(row + 8) * DIN + col - 2048] = s23;
                }
            }
        }
}

// ---------------------------------------------------------------------------
// fp32 SGEMM for the small delta GEMM (K=64): softplus(v + bias[col]) -> C
// ---------------------------------------------------------------------------
__global__ __launch_bounds__(256, 2)
void sgemm_sp_kernel(const float* __restrict__ A, int lda,
                     const float* __restrict__ B, int ldb,
                     float* __restrict__ C, int ldc,
                     const float* __restrict__ bias,
                     int M, int N, int K)
{
    __shared__ float As[2][16][132];
    __shared__ float Bs[2][16][128];

    const int tid = threadIdx.x;
    const int bm  = blockIdx.y * 128;
    const int bn  = blockIdx.x * 128;

    const int arow = tid >> 2;
    const int acol = (tid & 3) << 2;
    const int brow = tid >> 5;
    const int bcol = (tid & 31) << 2;
    const int tm = (tid >> 4) << 3;
    const int tn = (tid & 15) << 3;

    const float* Aptr  = A + (size_t)(bm + arow)      * lda + acol;
    const float* Aptr2 = A + (size_t)(bm + arow + 64) * lda + acol;
    const float* Bptr  = B + (size_t)brow       * ldb + bn + bcol;
    const float* Bptr2 = B + (size_t)(brow + 8) * ldb + bn + bcol;

    float acc[8][8];
#pragma unroll
    for (int i = 0; i < 8; ++i)
#pragma unroll
        for (int j = 0; j < 8; ++j) acc[i][j] = 0.0f;

    {
        float4 a0 = *(const float4*)Aptr;
        float4 a1 = *(const float4*)Aptr2;
        float4 b0 = *(const float4*)Bptr;
        float4 b1 = *(const float4*)Bptr2;
        As[0][acol + 0][arow]      = a0.x; As[0][acol + 1][arow]      = a0.y;
        As[0][acol + 2][arow]      = a0.z; As[0][acol + 3][arow]      = a0.w;
        As[0][acol + 0][arow + 64] = a1.x; As[0][acol + 1][arow + 64] = a1.y;
        As[0][acol + 2][arow + 64] = a1.z; As[0][acol + 3][arow + 64] = a1.w;
        *(float4*)&Bs[0][brow][bcol]     = b0;
        *(float4*)&Bs[0][brow + 8][bcol] = b1;
    }
    __syncthreads();

    const int nk = K >> 4;
    int buf = 0;
    for (int kt = 0; kt < nk; ++kt) {
        float4 na0, na1, nb0, nb1;
        const bool has_next = (kt + 1 < nk);
        if (has_next) {
            const int kof = (kt + 1) << 4;
            na0 = *(const float4*)(Aptr  + kof);
            na1 = *(const float4*)(Aptr2 + kof);
            nb0 = *(const float4*)(Bptr  + (size_t)kof * ldb);
            nb1 = *(const float4*)(Bptr2 + (size_t)kof * ldb);
        }
#pragma unroll
        for (int k = 0; k < 16; ++k) {
            float af[8], bf[8];
            *(float4*)&af[0] = *(const float4*)&As[buf][k][tm];
            *(float4*)&af[4] = *(const float4*)&As[buf][k][tm + 4];
            *(float4*)&bf[0] = *(const float4*)&Bs[buf][k][tn];
            *(float4*)&bf[4] = *(const float4*)&Bs[buf][k][tn + 4];
#pragma unroll
            for (int i = 0; i < 8; ++i)
#pragma unroll
                for (int j = 0; j < 8; ++j)
                    acc[i][j] = fmaf(af[i], bf[j], acc[i][j]);
        }
        if (has_next) {
            buf ^= 1;
            As[buf][acol + 0][arow]      = na0.x; As[buf][acol + 1][arow]      = na0.y;
            As[buf][acol + 2][arow]      = na0.z; As[buf][acol + 3][arow]      = na0.w;
            As[buf][acol + 0][arow + 64] = na1.x; As[buf][acol + 1][arow + 64] = na1.y;
            As[buf][acol + 2][arow + 64] = na1.z; As[buf][acol + 3][arow + 64] = na1.w;
            *(float4*)&Bs[buf][brow][bcol]     = nb0;
            *(float4*)&Bs[buf][brow + 8][bcol] = nb1;
            __syncthreads();
        }
    }

    const int row0 = bm + tm;
    float bz[8];
#pragma unroll
    for (int j = 0; j < 8; ++j) bz[j] = bias[bn + tn + j];
#pragma unroll
    for (int i = 0; i < 8; ++i) {
        float v[8];
#pragma unroll
        for (int j = 0; j < 8; ++j) v[j] = softplus_f(acc[i][j] + bz[j]);
        float* p = C + (size_t)(row0 + i) * ldc + bn + tn;
        *(float4*)p       = make_float4(v[0], v[1], v[2], v[3]);
        *(float4*)(p + 4) = make_float4(v[4], v[5], v[6], v[7]);
    }
}

// ---------------------------------------------------------------------------
// Causal depthwise conv (D_CONV=4) + silu
// ---------------------------------------------------------------------------
__global__ void conv_silu_kernel(const float* __restrict__ cw,
                                 const float* __restrict__ cb)
{
    const int idx = blockIdx.x * 256 + threadIdx.x;
    const int t = idx >> 11;
    const int d = idx & (DIN - 1);
    const float4 w = ((const float4*)cw)[d];
    float acc = cb[d];
    if (t >= 3) acc = fmaf(g_xc[idx - 3 * DIN], w.x, acc);
    if (t >= 2) acc = fmaf(g_xc[idx - 2 * DIN], w.y, acc);
    if (t >= 1) acc = fmaf(g_xc[idx - 1 * DIN], w.z, acc);
    acc = fmaf(g_xc[idx], w.w, acc);
    g_u[idx] = siluf(acc);
}

// ---------------------------------------------------------------------------
// x_dbl = u @ W_x  (M=2048, N=96, K=2048) split-K=32 + deterministic reduce
// ---------------------------------------------------------------------------
__global__ __launch_bounds__(256)
void xdbl_kernel(const float* __restrict__ Wx)
{
    __shared__ float As[16][132];
    __shared__ float Bs[16][XDBL_N];
    const int tid = threadIdx.x;
    const int bm  = blockIdx.x * 128;
    const int k0  = blockIdx.y * (DIN / KSPLIT);

    const int arow = tid >> 2;
    const int acol = (tid & 3) << 2;
    const int tm = (tid >> 4) << 3;
    const int tn = (tid & 15) * 6;

    float acc[8][6];
#pragma unroll
    for (int i = 0; i < 8; ++i)
#pragma unroll
        for (int j = 0; j < 6; ++j) acc[i][j] = 0.0f;

    const int NT = (DIN / KSPLIT) >> 4;
    for (int kt = 0; kt < NT; ++kt) {
        const int kof = k0 + (kt << 4);
        float4 a0 = *(const float4*)(g_u + (size_t)(bm + arow)      * DIN + kof + acol);
        float4 a1 = *(const float4*)(g_u + (size_t)(bm + arow + 64) * DIN + kof + acol);
        float bv[6];
#pragma unroll
        for (int i = 0; i < 6; ++i) {
            const int idx = tid + (i << 8);
            bv[i] = Wx[(size_t)(kof + idx / XDBL_N) * XDBL_N + (idx % XDBL_N)];
        }
        __syncthreads();
        As[acol + 0][arow]      = a0.x; As[acol + 1][arow]      = a0.y;
        As[acol + 2][arow]      = a0.z; As[acol + 3][arow]      = a0.w;
        As[acol + 0][arow + 64] = a1.x; As[acol + 1][arow + 64] = a1.y;
        As[acol + 2][arow + 64] = a1.z; As[acol + 3][arow + 64] = a1.w;
#pragma unroll
        for (int i = 0; i < 6; ++i) {
            const int idx = tid + (i << 8);
            Bs[idx / XDBL_N][idx % XDBL_N] = bv[i];
        }
        __syncthreads();
#pragma unroll
        for (int k = 0; k < 16; ++k) {
            float af[8], bf[6];
            *(float4*)&af[0] = *(const float4*)&As[k][tm];
            *(float4*)&af[4] = *(const float4*)&As[k][tm + 4];
#pragma unroll
            for (int j = 0; j < 6; ++j) bf[j] = Bs[k][tn + j];
#pragma unroll
            for (int i = 0; i < 8; ++i)
#pragma unroll
                for (int j = 0; j < 6; ++j)
                    acc[i][j] = fmaf(af[i], bf[j], acc[i][j]);
        }
    }

    float* pp = g_part + (size_t)blockIdx.y * (L_SEQ * XDBL_N);
#pragma unroll
    for (int i = 0; i < 8; ++i)
#pragma unroll
        for (int j = 0; j < 6; ++j)
            pp[(size_t)(bm + tm + i) * XDBL_N + tn + j] = acc[i][j];
}

__global__ void xdbl_reduce_kernel()
{
    const int i = blockIdx.x * 256 + threadIdx.x;
    float s = 0.0f;
#pragma unroll
    for (int k = 0; k < KSPLIT; ++k) s += g_part[(size_t)k * (L_SEQ * XDBL_N) + i];
    g_xdbl[i] = s;
}

// ---------------------------------------------------------------------------
// Selective scan (16 lanes per channel; shfl reduce over states)
// ---------------------------------------------------------------------------
__global__ __launch_bounds__(256)
void scan_kernel(const float* __restrict__ Dp)
{
    const int gid = blockIdx.x * 256 + threadIdx.x;
    const int d = gid >> 4;
    const int n = gid & 15;

    const float Aa = g_A[(d << 4) + n];
    const float Dd = Dp[d];
    float h = 0.0f;

    const int UN = 8;
    float dt[UN], ut[UN], Bt[UN], Ct[UN], zt[UN];
#pragma unroll
    for (int i = 0; i < UN; ++i) {
        dt[i] = g_delta[(size_t)i * DIN + d];
        ut[i] = g_u    [(size_t)i * DIN + d];
        Bt[i] = g_xdbl [(size_t)i * XDBL_N + DTRANK + n];
        Ct[i] = g_xdbl [(size_t)i * XDBL_N + DTRANK + DSTATE + n];
        zt[i] = g_zs   [(size_t)i * DIN + d];
    }

    for (int t0 = 0; t0 < L_SEQ; t0 += UN) {
        float ndt[UN], nut[UN], nBt[UN], nCt[UN], nzt[UN];
        const int t1 = t0 + UN;
        if (t1 < L_SEQ) {
#pragma unroll
            for (int i = 0; i < UN; ++i) {
                ndt[i] = g_delta[(size_t)(t1 + i) * DIN + d];
                nut[i] = g_u    [(size_t)(t1 + i) * DIN + d];
                nBt[i] = g_xdbl [(size_t)(t1 + i) * XDBL_N + DTRANK + n];
                nCt[i] = g_xdbl [(size_t)(t1 + i) * XDBL_N + DTRANK + DSTATE + n];
                nzt[i] = g_zs   [(size_t)(t1 + i) * DIN + d];
            }
        }
#pragma unroll
        for (int i = 0; i < UN; ++i) {
            const float e = __expf(dt[i] * Aa);
            h = fmaf(e, h, dt[i] * ut[i] * Bt[i]);
            float p = h * Ct[i];
            p += __shfl_xor_sync(0xffffffffu, p, 8, 16);
            p += __shfl_xor_sync(0xffffffffu, p, 4, 16);
            p += __shfl_xor_sync(0xffffffffu, p, 2, 16);
            p += __shfl_xor_sync(0xffffffffu, p, 1, 16);
            if (n == 0)
                g_ys[(size_t)(t0 + i) * DIN + d] = (p + Dd * ut[i]) * zt[i];
        }
        if (t1 < L_SEQ) {
#pragma unroll
            for (int i = 0; i < UN; ++i) {
                dt[i] = ndt[i]; ut[i] = nut[i]; Bt[i] = nBt[i]; Ct[i] = nCt[i]; zt[i] = nzt[i];
            }
        }
    }
}

// ---------------------------------------------------------------------------
// kernel_launch
// ---------------------------------------------------------------------------
extern "C" void kernel_launch(void* const* d_in, const int* in_sizes, int n_in,
                              void* d_out, int out_size)
{
    const float* x      = (const float*)d_in[0];
    const float* W_in   = (const float*)d_in[1];
    const float* conv_w = (const float*)d_in[2];
    const float* conv_b = (const float*)d_in[3];
    const float* W_x    = (const float*)d_in[4];
    const float* W_dt   = (const float*)d_in[5];
    const float* b_dt   = (const float*)d_in[6];
    const float* A_log  = (const float*)d_in[7];
    const float* D_par  = (const float*)d_in[8];
    const float* W_out  = (const float*)d_in[9];
    float* out = (float*)d_out;

    float *p_xdbl, *p_delta, *p_ys;
    __nv_bfloat16 *pA1, *pB1, *pA3, *pB3;
    cudaGetSymbolAddress((void**)&p_xdbl,  g_xdbl);
    cudaGetSymbolAddress((void**)&p_delta, g_delta);
    cudaGetSymbolAddress((void**)&p_ys,    g_ys);
    cudaGetSymbolAddress((void**)&pA1, g_A1);
    cudaGetSymbolAddress((void**)&pB1, g_B1);
    cudaGetSymbolAddress((void**)&pA3, g_A3);
    cudaGetSymbolAddress((void**)&pB3, g_B3);

    // 1. A = -exp(A_log)
    aprep_kernel<<<(DIN * DSTATE) / 256, 256>>>(A_log);

    // 2. bf16 split conversions
    split_act_kernel<<<(L_SEQ * DMODEL) / 256, 256>>>(x, pA1, DMODEL);
    wsplit_kernel<<<dim3((2 * DIN) / 32, DMODEL / 32), 256>>>(W_in, pB1, DMODEL, 2 * DIN);
    wsplit_kernel<<<dim3(DMODEL / 32, DIN / 32), 256>>>(W_out, pB3, DIN, DMODEL);

    // 3. GEMM1 (HMMA, BM=128): xz = x @ W_in -> g_xc | silu -> g_zs
    mma_gemm_kernel<1, 2><<<dim3((2 * DIN) / 128, L_SEQ / 128), 256>>>(
        pA1, pB1, nullptr, K1P, 0);

    // 4. u = silu(causal_conv(xc))
    conv_silu_kernel<<<(L_SEQ * DIN) / 256, 256>>>(conv_w, conv_b);

    // 5. x_dbl = u @ W_x  (split-K + deterministic reduce)
    xdbl_kernel<<<dim3(L_SEQ / 128, KSPLIT), 256>>>(W_x);
    xdbl_reduce_kernel<<<(L_SEQ * XDBL_N) / 256, 256>>>();

    // 6. delta = softplus(x_dbl[:, :64] @ W_dt + b_dt)  (fp32, K=64)
    sgemm_sp_kernel<<<dim3(DIN / 128, L_SEQ / 128), 256>>>(
        p_xdbl, XDBL_N, W_dt, DIN, p_delta, DIN, b_dt,
        L_SEQ, DIN, DTRANK);

    // 7. selective scan -> ys = y * silu(z)
    scan_kernel<<<(DIN * DSTATE) / 256, 256>>>(D_par);

    // 8. GEMM3 (HMMA, BM=64 -> 256 CTAs): out = ys @ W_out
    split_act_kernel<<<(L_SEQ * DIN) / 256, 256>>>(p_ys, pA3, DIN);
    mma_gemm_kernel<0, 1><<<dim3(DMODEL / 128, L_SEQ / 64), 256>>>(
        pA3, pB3, out, K3P, DMODEL);
}

// round 9
// speedup vs baseline: 2.5852x; 1.1548x over previous
#include <cuda_runtime.h>
#include <cuda_bf16.h>
#include <math.h>
#include <stdint.h>

// ---------------------------------------------------------------------------
// Problem constants
// ---------------------------------------------------------------------------
#define L_SEQ    2048
#define DMODEL   1024
#define DIN      2048   // D_INNER
#define DSTATE   16
#define DTRANK   64
#define XDBL_N   96     // DT_RANK + 2*D_STATE
#define KSPLIT   32     // split-K factor for the tall-skinny x_dbl GEMM

#define K1P (3 * DMODEL)   // 3072 : split-K' for GEMM1
#define K3P (3 * DIN)      // 6144 : split-K' for GEMM3

// ---------------------------------------------------------------------------
// Device scratch (no allocations allowed -> __device__ globals)
// ---------------------------------------------------------------------------
__device__ float g_xc   [L_SEQ * DIN];
__device__ float g_zs   [L_SEQ * DIN];
__device__ float g_u    [L_SEQ * DIN];
__device__ float g_delta[L_SEQ * DIN];
__device__ float g_ys   [L_SEQ * DIN];
__device__ float g_xdbl [L_SEQ * XDBL_N];
__device__ float g_part [KSPLIT * L_SEQ * XDBL_N];
__device__ float g_A    [DIN * DSTATE];

// bf16 split buffers (16B-aligned for cp.async / uint4)
__device__ __align__(128) __nv_bfloat16 g_A1[L_SEQ * K1P];     // [hi|lo|hi] of x
__device__ __align__(128) __nv_bfloat16 g_B1[2 * DIN * K1P];   // [hi|hi|lo] of W_in^T
__device__ __align__(128) __nv_bfloat16 g_A3[L_SEQ * K3P];     // split of ys
__device__ __align__(128) __nv_bfloat16 g_B3[DMODEL * K3P];    // split of W_out^T

// ---------------------------------------------------------------------------
// Helpers
// ---------------------------------------------------------------------------
__device__ __forceinline__ float siluf(float x) {
    return x / (1.0f + __expf(-x));
}
__device__ __forceinline__ float softplus_f(float x) {
    return x > 20.0f ? x : log1pf(__expf(x));
}
static __device__ __forceinline__ uint32_t smem_u32(const void* p) {
    uint32_t a;
    asm("{ .reg .u64 t; cvta.to.shared.u64 t, %1; cvt.u32.u64 %0, t; }" : "=r"(a) : "l"(p));
    return a;
}
static __device__ __forceinline__ void cp_async16(uint32_t saddr, const void* gptr) {
    asm volatile("cp.async.cg.shared.global [%0], [%1], 16;" :: "r"(saddr), "l"(gptr));
}
static __device__ __forceinline__ uint32_t pack_bf2(float a, float b) {
    __nv_bfloat162 h = __floats2bfloat162_rn(a, b);
    return *reinterpret_cast<uint32_t*>(&h);
}

// ---------------------------------------------------------------------------
// A = -exp(A_log)
// ---------------------------------------------------------------------------
__global__ void aprep_kernel(const float* __restrict__ A_log) {
    int i = blockIdx.x * 256 + threadIdx.x;
    g_A[i] = -__expf(A_log[i]);
}

// ---------------------------------------------------------------------------
// Split activation fp32 -> bf16 [hi | lo | hi], row stride 3K. float4 I/O.
// grid covers M*K/4 threads.
// ---------------------------------------------------------------------------
__global__ void split_act_kernel(const float* __restrict__ in,
                                 __nv_bfloat16* __restrict__ out, int K)
{
    const int idx = blockIdx.x * 256 + threadIdx.x;     // over M*K/4
    const int Kq = K >> 2;
    const int r = idx / Kq;
    const int c4 = (idx - r * Kq) << 2;
    float4 v = ((const float4*)in)[idx];

    float hx = __bfloat162float(__float2bfloat16(v.x));
    float hy = __bfloat162float(__float2bfloat16(v.y));
    float hz = __bfloat162float(__float2bfloat16(v.z));
    float hw = __bfloat162float(__float2bfloat16(v.w));

    uint2 hi = make_uint2(pack_bf2(v.x, v.y), pack_bf2(v.z, v.w));
    uint2 lo = make_uint2(pack_bf2(v.x - hx, v.y - hy), pack_bf2(v.z - hz, v.w - hw));

    __nv_bfloat16* base = out + (size_t)r * (3 * K) + c4;
    *(uint2*)(base)         = hi;
    *(uint2*)(base + K)     = lo;
    *(uint2*)(base + 2 * K) = hi;
}

// ---------------------------------------------------------------------------
// Transpose + split weights: W[K,N] fp32 -> out[N, 3K] bf16 as [hi | hi | lo].
// ---------------------------------------------------------------------------
__global__ void wsplit_kernel(const float* __restrict__ W,
                              __nv_bfloat16* __restrict__ out, int K, int N)
{
    __shared__ float t[32][33];
    const int tx = threadIdx.x & 31;
    const int ty = threadIdx.x >> 5;    // 0..7
    const int col = blockIdx.x * 32 + tx;
#pragma unroll
    for (int i = 0; i < 4; ++i) {
        int row = blockIdx.y * 32 + ty + i * 8;
        t[ty + i * 8][tx] = W[(size_t)row * N + col];
    }
    __syncthreads();
    const int k = blockIdx.y * 32 + tx;
    const int K3 = 3 * K;
#pragma unroll
    for (int i = 0; i < 4; ++i) {
        int n = blockIdx.x * 32 + ty + i * 8;
        float v = t[tx][ty + i * 8];
        __nv_bfloat16 h = __float2bfloat16(v);
        __nv_bfloat16 l = __float2bfloat16(v - __bfloat162float(h));
        size_t base = (size_t)n * K3;
        out[base + k]         = h;
        out[base + K + k]     = h;
        out[base + 2 * K + k] = l;
    }
}

// ---------------------------------------------------------------------------
// HMMA (mma.sync m16n8k16 bf16) GEMM:  D[M,N] = A'[M,Kp] @ B'[N,Kp]^T
// BM=MF*64, BN=128, BK=32, 256 threads = 8 warps (4m x 2n).
// MF=2: single frag set (register-safe at 2 CTAs/SM).
// MF=1: fragment double-buffer pipeline (fits 128 regs).
// EPI 0: C[row*ldc + col] = v                 (GEMM3 -> out)
// EPI 1: col<2048 -> g_xc ; else silu -> g_zs (GEMM1)
// ---------------------------------------------------------------------------
#define SSTR 40   // smem row stride in bf16 (80 bytes)

template<int MF>
static __device__ __forceinline__ void ld_frags(
    uint32_t sa, uint32_t sb, int a_r0, int a_kc, int b_r0, int b_kc, int ks,
    uint32_t (&a)[MF][4], uint32_t (&b)[4][4])
{
#pragma unroll
    for (int mf = 0; mf < MF; ++mf) {
        uint32_t ad = sa + (uint32_t)((a_r0 + mf * 16) * SSTR + ks * 16 + a_kc) * 2;
        asm volatile("ldmatrix.sync.aligned.m8n8.x4.shared.b16 {%0,%1,%2,%3}, [%4];"
                     : "=r"(a[mf][0]), "=r"(a[mf][1]), "=r"(a[mf][2]), "=r"(a[mf][3])
                     : "r"(ad));
    }
#pragma unroll
    for (int nq = 0; nq < 4; ++nq) {
        uint32_t bd = sb + (uint32_t)((b_r0 + nq * 16) * SSTR + ks * 16 + b_kc) * 2;
        asm volatile("ldmatrix.sync.aligned.m8n8.x4.shared.b16 {%0,%1,%2,%3}, [%4];"
                     : "=r"(b[nq][0]), "=r"(b[nq][1]), "=r"(b[nq][2]), "=r"(b[nq][3])
                     : "r"(bd));
    }
}

template<int MF>
static __device__ __forceinline__ void do_mma(
    float (&acc)[MF][8][4], uint32_t (&a)[MF][4], uint32_t (&b)[4][4])
{
#pragma unroll
    for (int mf = 0; mf < MF; ++mf)
#pragma unroll
        for (int nf = 0; nf < 8; ++nf) {
            uint32_t b0 = b[nf >> 1][(nf & 1) << 1];
            uint32_t b1 = b[nf >> 1][((nf & 1) << 1) + 1];
            asm volatile(
                "mma.sync.aligned.m16n8k16.row.col.f32.bf16.bf16.f32 "
                "{%0,%1,%2,%3}, {%4,%5,%6,%7}, {%8,%9}, {%0,%1,%2,%3};"
                : "+f"(acc[mf][nf][0]), "+f"(acc[mf][nf][1]),
                  "+f"(acc[mf][nf][2]), "+f"(acc[mf][nf][3])
                : "r"(a[mf][0]), "r"(a[mf][1]), "r"(a[mf][2]), "r"(a[mf][3]),
                  "r"(b0), "r"(b1));
        }
}

template<int EPI, int MF>
__global__ __launch_bounds__(256, 2)
void mma_gemm_kernel(const __nv_bfloat16* __restrict__ Ab,
                     const __nv_bfloat16* __restrict__ Bb,
                     float* __restrict__ C, int Kp, int ldc)
{
    constexpr int BM = MF * 64;
    __shared__ __nv_bfloat16 sA[2][BM * SSTR];
    __shared__ __nv_bfloat16 sB[2][128 * SSTR];

    const int tid  = threadIdx.x;
    const int lane = tid & 31;
    const int wid  = tid >> 5;
    const int mw   = wid >> 1;       // 0..3
    const int nw   = wid & 1;        // 0..1
    const int bm   = blockIdx.y * BM;
    const int bn   = blockIdx.x * 128;

    const int KpV = Kp >> 3;                       // row stride in uint4
    const uint4* Ag = (const uint4*)Ab + (size_t)bm * KpV;
    const uint4* Bg = (const uint4*)Bb + (size_t)bn * KpV;

    const int lr = tid >> 2;        // load row 0..63 (and +64)
    const int lc = tid & 3;         // 16B chunk 0..3

    float acc[MF][8][4];
#pragma unroll
    for (int mf = 0; mf < MF; ++mf)
#pragma unroll
        for (int nf = 0; nf < 8; ++nf)
#pragma unroll
            for (int q = 0; q < 4; ++q) acc[mf][nf][q] = 0.0f;

    // ldmatrix lane offsets
    const int a_r0 = mw * (16 * MF) + (lane & 15);
    const int a_kc = ((lane >> 4) << 3);
    const int b_r0 = nw * 64 + (lane & 7) + ((lane >> 4) << 3);
    const int b_kc = (((lane >> 3) & 1) << 3);

    const int nkt = Kp >> 5;    // BK=32 iterations

    auto load_tile = [&](int b, int kt) {
        const int kof = kt << 2;   // uint4 offset
        uint32_t sa = smem_u32(&sA[b][0]);
        uint32_t sb = smem_u32(&sB[b][0]);
        cp_async16(sa + (uint32_t)(lr * SSTR + lc * 8) * 2, Ag + (size_t)lr * KpV + kof + lc);
        if (MF == 2)
            cp_async16(sa + (uint32_t)((lr + 64) * SSTR + lc * 8) * 2,
                       Ag + (size_t)(lr + 64) * KpV + kof + lc);
        cp_async16(sb + (uint32_t)(lr * SSTR + lc * 8) * 2, Bg + (size_t)lr * KpV + kof + lc);
        cp_async16(sb + (uint32_t)((lr + 64) * SSTR + lc * 8) * 2,
                   Bg + (size_t)(lr + 64) * KpV + kof + lc);
        asm volatile("cp.async.commit_group;" ::: "memory");
    };

    // prologue
    load_tile(0, 0);
    asm volatile("cp.async.wait_group 0;" ::: "memory");
    __syncthreads();

    int buf = 0;
    if (MF == 2) {
        // register-safe mainloop: single fragment set
        uint32_t fa[MF][4], fb[4][4];
        for (int kt = 0; kt < nkt; ++kt) {
            const bool has_next = (kt + 1 < nkt);
            if (has_next) load_tile(buf ^ 1, kt + 1);
            const uint32_t sa = smem_u32(&sA[buf][0]);
            const uint32_t sb = smem_u32(&sB[buf][0]);
#pragma unroll
            for (int ks = 0; ks < 2; ++ks) {
                ld_frags<MF>(sa, sb, a_r0, a_kc, b_r0, b_kc, ks, fa, fb);
                do_mma<MF>(acc, fa, fb);
            }
            if (has_next) {
                asm volatile("cp.async.wait_group 0;" ::: "memory");
                __syncthreads();
            }
            buf ^= 1;
        }
    } else {
        // pipelined mainloop: fragment double buffer
        uint32_t fa0[MF][4], fb0[4][4];
        uint32_t fa1[MF][4], fb1[4][4];
        {
            uint32_t sa = smem_u32(&sA[0][0]);
            uint32_t sb = smem_u32(&sB[0][0]);
            ld_frags<MF>(sa, sb, a_r0, a_kc, b_r0, b_kc, 0, fa0, fb0);
        }
        for (int kt = 0; kt < nkt; ++kt) {
            const bool has_next = (kt + 1 < nkt);
            if (has_next) load_tile(buf ^ 1, kt + 1);
            {
                uint32_t sa = smem_u32(&sA[buf][0]);
                uint32_t sb = smem_u32(&sB[buf][0]);
                ld_frags<MF>(sa, sb, a_r0, a_kc, b_r0, b_kc, 1, fa1, fb1);
            }
            do_mma<MF>(acc, fa0, fb0);
            if (has_next) {
                asm volatile("cp.async.wait_group 0;" ::: "memory");
                __syncthreads();
                uint32_t sa = smem_u32(&sA[buf ^ 1][0]);
                uint32_t sb = smem_u32(&sB[buf ^ 1][0]);
                ld_frags<MF>(sa, sb, a_r0, a_kc, b_r0, b_kc, 0, fa0, fb0);
            }
            do_mma<MF>(acc, fa1, fb1);
            buf ^= 1;
        }
    }

    // ---- epilogue
    const int rbase = bm + mw * (16 * MF) + (lane >> 2);
    const int cbase = bn + nw * 64 + ((lane & 3) << 1);
#pragma unroll
    for (int mf = 0; mf < MF; ++mf)
#pragma unroll
        for (int nf = 0; nf < 8; ++nf) {
            const int row = rbase + mf * 16;
            const int col = cbase + nf * 8;
            float2 v01 = make_float2(acc[mf][nf][0], acc[mf][nf][1]);
            float2 v23 = make_float2(acc[mf][nf][2], acc[mf][nf][3]);
            if (EPI == 0) {
                *(float2*)&C[(size_t)row * ldc + col]       = v01;
                *(float2*)&C[(size_t)(row + 8) * ldc + col] = v23;
            } else {
                if (col < 2048) {
                    *(float2*)&g_xc[(size_t)row * DIN + col]       = v01;
                    *(float2*)&g_xc[(size_t)(row + 8) * DIN + col] = v23;
                } else {
                    float2 s01 = make_float2(siluf(v01.x), siluf(v01.y));
                    float2 s23 = make_float2(siluf(v23.x), siluf(v23.y));
                    *(float2*)&g_zs[(size_t)row * DIN + col - 2048]       = s01;
                    *(float2*)&g_zs[(size_t)(row + 8) * DIN + col - 2048] = s23;
                }
            }
        }
}

// ---------------------------------------------------------------------------
// fp32 SGEMM for the small delta GEMM (K=64): softplus(v + bias[col]) -> C
// ---------------------------------------------------------------------------
__global__ __launch_bounds__(256, 2)
void sgemm_sp_kernel(const float* __restrict__ A, int lda,
                     const float* __restrict__ B, int ldb,
                     float* __restrict__ C, int ldc,
                     const float* __restrict__ bias,
                     int M, int N, int K)
{
    __shared__ float As[2][16][132];
    __shared__ float Bs[2][16][128];

    const int tid = threadIdx.x;
    const int bm  = blockIdx.y * 128;
    const int bn  = blockIdx.x * 128;

    const int arow = tid >> 2;
    const int acol = (tid & 3) << 2;
    const int brow = tid >> 5;
    const int bcol = (tid & 31) << 2;
    const int tm = (tid >> 4) << 3;
    const int tn = (tid & 15) << 3;

    const float* Aptr  = A + (size_t)(bm + arow)      * lda + acol;
    const float* Aptr2 = A + (size_t)(bm + arow + 64) * lda + acol;
    const float* Bptr  = B + (size_t)brow       * ldb + bn + bcol;
    const float* Bptr2 = B + (size_t)(brow + 8) * ldb + bn + bcol;

    float acc[8][8];
#pragma unroll
    for (int i = 0; i < 8; ++i)
#pragma unroll
        for (int j = 0; j < 8; ++j) acc[i][j] = 0.0f;

    {
        float4 a0 = *(const float4*)Aptr;
        float4 a1 = *(const float4*)Aptr2;
        float4 b0 = *(const float4*)Bptr;
        float4 b1 = *(const float4*)Bptr2;
        As[0][acol + 0][arow]      = a0.x; As[0][acol + 1][arow]      = a0.y;
        As[0][acol + 2][arow]      = a0.z; As[0][acol + 3][arow]      = a0.w;
        As[0][acol + 0][arow + 64] = a1.x; As[0][acol + 1][arow + 64] = a1.y;
        As[0][acol + 2][arow + 64] = a1.z; As[0][acol + 3][arow + 64] = a1.w;
        *(float4*)&Bs[0][brow][bcol]     = b0;
        *(float4*)&Bs[0][brow + 8][bcol] = b1;
    }
    __syncthreads();

    const int nk = K >> 4;
    int buf = 0;
    for (int kt = 0; kt < nk; ++kt) {
        float4 na0, na1, nb0, nb1;
        const bool has_next = (kt + 1 < nk);
        if (has_next) {
            const int kof = (kt + 1) << 4;
            na0 = *(const float4*)(Aptr  + kof);
            na1 = *(const float4*)(Aptr2 + kof);
            nb0 = *(const float4*)(Bptr  + (size_t)kof * ldb);
            nb1 = *(const float4*)(Bptr2 + (size_t)kof * ldb);
        }
#pragma unroll
        for (int k = 0; k < 16; ++k) {
            float af[8], bf[8];
            *(float4*)&af[0] = *(const float4*)&As[buf][k][tm];
            *(float4*)&af[4] = *(const float4*)&As[buf][k][tm + 4];
            *(float4*)&bf[0] = *(const float4*)&Bs[buf][k][tn];
            *(float4*)&bf[4] = *(const float4*)&Bs[buf][k][tn + 4];
#pragma unroll
            for (int i = 0; i < 8; ++i)
#pragma unroll
                for (int j = 0; j < 8; ++j)
                    acc[i][j] = fmaf(af[i], bf[j], acc[i][j]);
        }
        if (has_next) {
            buf ^= 1;
            As[buf][acol + 0][arow]      = na0.x; As[buf][acol + 1][arow]      = na0.y;
            As[buf][acol + 2][arow]      = na0.z; As[buf][acol + 3][arow]      = na0.w;
            As[buf][acol + 0][arow + 64] = na1.x; As[buf][acol + 1][arow + 64] = na1.y;
            As[buf][acol + 2][arow + 64] = na1.z; As[buf][acol + 3][arow + 64] = na1.w;
            *(float4*)&Bs[buf][brow][bcol]     = nb0;
            *(float4*)&Bs[buf][brow + 8][bcol] = nb1;
            __syncthreads();
        }
    }

    const int row0 = bm + tm;
    float bz[8];
#pragma unroll
    for (int j = 0; j < 8; ++j) bz[j] = bias[bn + tn + j];
#pragma unroll
    for (int i = 0; i < 8; ++i) {
        float v[8];
#pragma unroll
        for (int j = 0; j < 8; ++j) v[j] = softplus_f(acc[i][j] + bz[j]);
        float* p = C + (size_t)(row0 + i) * ldc + bn + tn;
        *(float4*)p       = make_float4(v[0], v[1], v[2], v[3]);
        *(float4*)(p + 4) = make_float4(v[4], v[5], v[6], v[7]);
    }
}

// ---------------------------------------------------------------------------
// Causal depthwise conv (D_CONV=4) + silu, 4 channels per thread (float4 I/O)
// ---------------------------------------------------------------------------
__global__ void conv_silu_kernel(const float* __restrict__ cw,
                                 const float* __restrict__ cb)
{
    const int idx = blockIdx.x * 256 + threadIdx.x;   // over L*DIN/4
    const int t  = idx >> 9;            // / (DIN/4)
    const int d4 = idx & 511;
    const int d  = d4 << 2;

    const float4 w0 = ((const float4*)cw)[d + 0];   // taps of channel d
    const float4 w1 = ((const float4*)cw)[d + 1];
    const float4 w2 = ((const float4*)cw)[d + 2];
    const float4 w3 = ((const float4*)cw)[d + 3];
    float4 acc = *(const float4*)&cb[d];

    const float* base = g_xc + (size_t)t * DIN + d;
    float4 xv = *(const float4*)base;                       // tap j=3
    acc.x = fmaf(xv.x, w0.w, acc.x); acc.y = fmaf(xv.y, w1.w, acc.y);
    acc.z = fmaf(xv.z, w2.w, acc.z); acc.w = fmaf(xv.w, w3.w, acc.w);
    if (t >= 1) {
        float4 v = *(const float4*)(base - DIN);            // tap j=2
        acc.x = fmaf(v.x, w0.z, acc.x); acc.y = fmaf(v.y, w1.z, acc.y);
        acc.z = fmaf(v.z, w2.z, acc.z); acc.w = fmaf(v.w, w3.z, acc.w);
    }
    if (t >= 2) {
        float4 v = *(const float4*)(base - 2 * DIN);        // tap j=1
        acc.x = fmaf(v.x, w0.y, acc.x); acc.y = fmaf(v.y, w1.y, acc.y);
        acc.z = fmaf(v.z, w2.y, acc.z); acc.w = fmaf(v.w, w3.y, acc.w);
    }
    if (t >= 3) {
        float4 v = *(const float4*)(base - 3 * DIN);        // tap j=0
        acc.x = fmaf(v.x, w0.x, acc.x); acc.y = fmaf(v.y, w1.x, acc.y);
        acc.z = fmaf(v.z, w2.x, acc.z); acc.w = fmaf(v.w, w3.x, acc.w);
    }
    float4 r = make_float4(siluf(acc.x), siluf(acc.y), siluf(acc.z), siluf(acc.w));
    *(float4*)(g_u + (size_t)t * DIN + d) = r;
}

// ---------------------------------------------------------------------------
// x_dbl = u @ W_x  (M=2048, N=96, K=2048) split-K=32 + deterministic reduce
// ---------------------------------------------------------------------------
__global__ __launch_bounds__(256)
void xdbl_kernel(const float* __restrict__ Wx)
{
    __shared__ float As[16][132];
    __shared__ float Bs[16][XDBL_N];
    const int tid = threadIdx.x;
    const int bm  = blockIdx.x * 128;
    const int k0  = blockIdx.y * (DIN / KSPLIT);

    const int arow = tid >> 2;
    const int acol = (tid & 3) << 2;
    const int tm = (tid >> 4) << 3;
    const int tn = (tid & 15) * 6;

    float acc[8][6];
#pragma unroll
    for (int i = 0; i < 8; ++i)
#pragma unroll
        for (int j = 0; j < 6; ++j) acc[i][j] = 0.0f;

    const int NT = (DIN / KSPLIT) >> 4;
    for (int kt = 0; kt < NT; ++kt) {
        const int kof = k0 + (kt << 4);
        float4 a0 = *(const float4*)(g_u + (size_t)(bm + arow)      * DIN + kof + acol);
        float4 a1 = *(const float4*)(g_u + (size_t)(bm + arow + 64) * DIN + kof + acol);
        float bv[6];
#pragma unroll
        for (int i = 0; i < 6; ++i) {
            const int idx = tid + (i << 8);
            bv[i] = Wx[(size_t)(kof + idx / XDBL_N) * XDBL_N + (idx % XDBL_N)];
        }
        __syncthreads();
        As[acol + 0][arow]      = a0.x; As[acol + 1][arow]      = a0.y;
        As[acol + 2][arow]      = a0.z; As[acol + 3][arow]      = a0.w;
        As[acol + 0][arow + 64] = a1.x; As[acol + 1][arow + 64] = a1.y;
        As[acol + 2][arow + 64] = a1.z; As[acol + 3][arow + 64] = a1.w;
#pragma unroll
        for (int i = 0; i < 6; ++i) {
            const int idx = tid + (i << 8);
            Bs[idx / XDBL_N][idx % XDBL_N] = bv[i];
        }
        __syncthreads();
#pragma unroll
        for (int k = 0; k < 16; ++k) {
            float af[8], bf[6];
            *(float4*)&af[0] = *(const float4*)&As[k][tm];
            *(float4*)&af[4] = *(const float4*)&As[k][tm + 4];
#pragma unroll
            for (int j = 0; j < 6; ++j) bf[j] = Bs[k][tn + j];
#pragma unroll
            for (int i = 0; i < 8; ++i)
#pragma unroll
                for (int j = 0; j < 6; ++j)
                    acc[i][j] = fmaf(af[i], bf[j], acc[i][j]);
        }
    }

    float* pp = g_part + (size_t)blockIdx.y * (L_SEQ * XDBL_N);
#pragma unroll
    for (int i = 0; i < 8; ++i)
#pragma unroll
        for (int j = 0; j < 6; ++j)
            pp[(size_t)(bm + tm + i) * XDBL_N + tn + j] = acc[i][j];
}

__global__ void xdbl_reduce_kernel()
{
    const int i = blockIdx.x * 256 + threadIdx.x;     // over L*96/4
    float4 s = make_float4(0.f, 0.f, 0.f, 0.f);
#pragma unroll
    for (int k = 0; k < KSPLIT; ++k) {
        float4 v = *(const float4*)&g_part[(size_t)k * (L_SEQ * XDBL_N) + i * 4];
        s.x += v.x; s.y += v.y; s.z += v.z; s.w += v.w;
    }
    *(float4*)&g_xdbl[i * 4] = s;
}

// ---------------------------------------------------------------------------
// Selective scan (16 lanes per channel; shfl reduce over states). 128-thr blocks.
// ---------------------------------------------------------------------------
__global__ __launch_bounds__(128)
void scan_kernel(const float* __restrict__ Dp)
{
    const int gid = blockIdx.x * 128 + threadIdx.x;
    const int d = gid >> 4;
    const int n = gid & 15;

    const float Aa = g_A[(d << 4) + n];
    const float Dd = Dp[d];
    float h = 0.0f;

    const int UN = 8;
    float dt[UN], ut[UN], Bt[UN], Ct[UN], zt[UN];
#pragma unroll
    for (int i = 0; i < UN; ++i) {
        dt[i] = g_delta[(size_t)i * DIN + d];
        ut[i] = g_u    [(size_t)i * DIN + d];
        Bt[i] = g_xdbl [(size_t)i * XDBL_N + DTRANK + n];
        Ct[i] = g_xdbl [(size_t)i * XDBL_N + DTRANK + DSTATE + n];
        zt[i] = g_zs   [(size_t)i * DIN + d];
    }

    for (int t0 = 0; t0 < L_SEQ; t0 += UN) {
        float ndt[UN], nut[UN], nBt[UN], nCt[UN], nzt[UN];
        const int t1 = t0 + UN;
        if (t1 < L_SEQ) {
#pragma unroll
            for (int i = 0; i < UN; ++i) {
                ndt[i] = g_delta[(size_t)(t1 + i) * DIN + d];
                nut[i] = g_u    [(size_t)(t1 + i) * DIN + d];
                nBt[i] = g_xdbl [(size_t)(t1 + i) * XDBL_N + DTRANK + n];
                nCt[i] = g_xdbl [(size_t)(t1 + i) * XDBL_N + DTRANK + DSTATE + n];
                nzt[i] = g_zs   [(size_t)(t1 + i) * DIN + d];
            }
        }
#pragma unroll
        for (int i = 0; i < UN; ++i) {
            const float e = __expf(dt[i] * Aa);
            h = fmaf(e, h, dt[i] * ut[i] * Bt[i]);
            float p = h * Ct[i];
            p += __shfl_xor_sync(0xffffffffu, p, 8, 16);
            p += __shfl_xor_sync(0xffffffffu, p, 4, 16);
            p += __shfl_xor_sync(0xffffffffu, p, 2, 16);
            p += __shfl_xor_sync(0xffffffffu, p, 1, 16);
            if (n == 0)
                g_ys[(size_t)(t0 + i) * DIN + d] = (p + Dd * ut[i]) * zt[i];
        }
        if (t1 < L_SEQ) {
#pragma unroll
            for (int i = 0; i < UN; ++i) {
                dt[i] = ndt[i]; ut[i] = nut[i]; Bt[i] = nBt[i]; Ct[i] = nCt[i]; zt[i] = nzt[i];
            }
        }
    }
}

// ---------------------------------------------------------------------------
// kernel_launch  (launch order arranged so GEMM1 is our 4th launch -> profiled)
// ---------------------------------------------------------------------------
extern "C" void kernel_launch(void* const* d_in, const int* in_sizes, int n_in,
                              void* d_out, int out_size)
{
    const float* x      = (const float*)d_in[0];
    const float* W_in   = (const float*)d_in[1];
    const float* conv_w = (const float*)d_in[2];
    const float* conv_b = (const float*)d_in[3];
    const float* W_x    = (const float*)d_in[4];
    const float* W_dt   = (const float*)d_in[5];
    const float* b_dt   = (const float*)d_in[6];
    const float* A_log  = (const float*)d_in[7];
    const float* D_par  = (const float*)d_in[8];
    const float* W_out  = (const float*)d_in[9];
    float* out = (float*)d_out;

    float *p_xdbl, *p_delta, *p_ys;
    __nv_bfloat16 *pA1, *pB1, *pA3, *pB3;
    cudaGetSymbolAddress((void**)&p_xdbl,  g_xdbl);
    cudaGetSymbolAddress((void**)&p_delta, g_delta);
    cudaGetSymbolAddress((void**)&p_ys,    g_ys);
    cudaGetSymbolAddress((void**)&pA1, g_A1);
    cudaGetSymbolAddress((void**)&pB1, g_B1);
    cudaGetSymbolAddress((void**)&pA3, g_A3);
    cudaGetSymbolAddress((void**)&pB3, g_B3);

    // 1. split of x for GEMM1
    split_act_kernel<<<(L_SEQ * DMODEL / 4) / 256, 256>>>(x, pA1, DMODEL);
    // 2. split+transpose of W_in
    wsplit_kernel<<<dim3((2 * DIN) / 32, DMODEL / 32), 256>>>(W_in, pB1, DMODEL, 2 * DIN);
    // 3. A = -exp(A_log)
    aprep_kernel<<<(DIN * DSTATE) / 256, 256>>>(A_log);
    // 4. GEMM1 (HMMA, BM=128): xz = x @ W_in -> g_xc | silu -> g_zs   [PROFILED]
    mma_gemm_kernel<1, 2><<<dim3((2 * DIN) / 128, L_SEQ / 128), 256>>>(
        pA1, pB1, nullptr, K1P, 0);
    // 5. u = silu(causal_conv(xc))
    conv_silu_kernel<<<(L_SEQ * DIN / 4) / 256, 256>>>(conv_w, conv_b);
    // 6. x_dbl = u @ W_x  (split-K + deterministic reduce)
    xdbl_kernel<<<dim3(L_SEQ / 128, KSPLIT), 256>>>(W_x);
    xdbl_reduce_kernel<<<(L_SEQ * XDBL_N / 4) / 256, 256>>>();
    // 7. delta = softplus(x_dbl[:, :64] @ W_dt + b_dt)  (fp32, K=64)
    sgemm_sp_kernel<<<dim3(DIN / 128, L_SEQ / 128), 256>>>(
        p_xdbl, XDBL_N, W_dt, DIN, p_delta, DIN, b_dt,
        L_SEQ, DIN, DTRANK);
    // 8. split+transpose of W_out (independent; anywhere before GEMM3)
    wsplit_kernel<<<dim3(DMODEL / 32, DIN / 32), 256>>>(W_out, pB3, DIN, DMODEL);
    // 9. selective scan -> ys = y * silu(z)
    scan_kernel<<<(DIN * DSTATE) / 128, 128>>>(D_par);
    // 10. split of ys; GEMM3 (HMMA, BM=64 -> 256 CTAs): out = ys @ W_out
    split_act_kernel<<<(L_SEQ * DIN / 4) / 256, 256>>>(p_ys, pA3, DIN);
    mma_gemm_kernel<0, 1><<<dim3(DMODEL / 128, L_SEQ / 64), 256>>>(
        pA3, pB3, out, K3P, DMODEL);
}